// round 6
// baseline (speedup 1.0000x reference)
#include <cuda_runtime.h>
#include <cstdint>

#define NN 50000
#define EE 800000
#define HH 3
#define HIDN 128
#define HF (HH*HIDN)   // 384
#define NCLS 6
#define MBLKS 391      // ceil(50000/128)

// weight-fragment scratch offsets (words)
#define WF_W1  0
#define WF_W2  98304
#define WF_L1  196608
#define WF_L2  229376
#define WF_L3  262144
#define WF_L4  294912
#define WF_TOT 327680

// ---------------- scratch (device globals; no allocation allowed) --------
__device__ float    g_h[NN*HF];     // post-GEMM per-head features
__device__ float    g_x[NN*HIDN];   // layer input / MLP ping
__device__ float    g_y[NN*HIDN];   // MLP pong
__device__ float    g_el[NN*HH];
__device__ float    g_er[NN*HH];
__device__ float    g_dnm[NN*HH];   // 1/denominator per (node, head)
__device__ float    g_alpha[3*EE];  // planar: [h][csr_pos], exp values
__device__ int      g_srcs[EE];     // src node id in CSR order
__device__ int      g_deg[NN];
__device__ int      g_rowptr[NN+1];
__device__ int      g_wptr[NN];
__device__ uint32_t g_wf[WF_TOT];           // pre-split weight frags (hi/lo)
__device__ uint32_t g_afrag[MBLKS*8*4096];  // pre-split A frags (hi/lo)

// ---------------- helpers -------------------------------------------------
__device__ __forceinline__ uint32_t cvt_tf32(float f) {
    uint32_t r;
    asm("cvt.rna.tf32.f32 %0, %1;" : "=r"(r) : "f"(f));
    return r;
}
__device__ __forceinline__ void mma8(float* c, const uint32_t* a, uint32_t b0, uint32_t b1) {
    asm("mma.sync.aligned.m16n8k8.row.col.f32.tf32.tf32.f32 "
        "{%0,%1,%2,%3}, {%4,%5,%6,%7}, {%8,%9}, {%0,%1,%2,%3};"
        : "+f"(c[0]), "+f"(c[1]), "+f"(c[2]), "+f"(c[3])
        : "r"(a[0]), "r"(a[1]), "r"(a[2]), "r"(a[3]), "r"(b0), "r"(b1));
}
// packed A-frag address for element (row, k); hi word; lo at +128
__device__ __forceinline__ int frag_addr(int row, int k) {
    int mblk = row >> 7, mtile = (row >> 4) & 7, r16 = row & 15;
    int ch = k >> 4, ks = (k >> 3) & 1, k8 = k & 7;
    int blk = mtile*2 + ks;
    int L   = (r16 & 7)*4 + (k8 & 3);
    int reg = (k8 >> 2)*2 + (r16 >> 3);
    return (((mblk*8 + ch)*16 + blk) << 8) + (L << 2) + reg;
}

// ---------------- pre-split kernels --------------------------------------
// Split all 6 weight matrices into tf32 hi/lo planes in B-fragment order.
__global__ void presplit_w_kernel(const float* __restrict__ W1, const float* __restrict__ W2,
                                  const float* __restrict__ L1, const float* __restrict__ L2,
                                  const float* __restrict__ L3, const float* __restrict__ L4)
{
    int i = blockIdx.x*blockDim.x + threadIdx.x;
    if (i >= 163840) return;
    const float* W; int ncols, ooff, rem;
    if      (i < 49152)  { W = W1; ncols = 384; ooff = WF_W1; rem = i; }
    else if (i < 98304)  { W = W2; ncols = 384; ooff = WF_W2; rem = i - 49152; }
    else if (i < 114688) { W = L1; ncols = 128; ooff = WF_L1; rem = i - 98304; }
    else if (i < 131072) { W = L2; ncols = 128; ooff = WF_L2; rem = i - 114688; }
    else if (i < 147456) { W = L3; ncols = 128; ooff = WF_L3; rem = i - 131072; }
    else                 { W = L4; ncols = 128; ooff = WF_L4; rem = i - 147456; }
    int g = rem >> 6, idx = rem & 63;
    int L = idx >> 1, kb = idx & 1;
    int nt = g & 7, wn = (g >> 3) & 1, ks = (g >> 4) & 1, ch = (g >> 5) & 7, cb = g >> 8;
    int k = ch*16 + ks*8 + (L & 3) + kb*4;
    int n = cb*128 + wn*64 + nt*8 + (L >> 2);
    float v = W[k*ncols + n];
    uint32_t hi = cvt_tf32(v);
    uint32_t lo = cvt_tf32(v - __uint_as_float(hi));
    g_wf[ooff + g*128 + L*4 + kb]     = hi;
    g_wf[ooff + g*128 + L*4 + 2 + kb] = lo;
}

// Split in_feat (50000x128, zero-padded to 50048) into A-fragment order.
__global__ void presplit_a_kernel(const float* __restrict__ X)
{
    int i = blockIdx.x*blockDim.x + threadIdx.x;
    if (i >= MBLKS*128*128) return;
    int row = i >> 7, k = i & 127;
    float v = (row < NN) ? X[row*128 + k] : 0.f;
    uint32_t hi = cvt_tf32(v);
    uint32_t lo = cvt_tf32(v - __uint_as_float(hi));
    int a = frag_addr(row, k);
    g_afrag[a]       = hi;
    g_afrag[a + 128] = lo;
}

// ---------------- CSR build ----------------------------------------------
__global__ void zero_deg_kernel() {
    int i = blockIdx.x*blockDim.x + threadIdx.x;
    if (i < NN) g_deg[i] = 0;
}

__global__ void hist_kernel(const int* __restrict__ dst) {
    int i = blockIdx.x*blockDim.x + threadIdx.x;
    if (i < EE) atomicAdd(&g_deg[dst[i]], 1);
}

__global__ void scan_kernel() {
    __shared__ int sh[1024];
    int t = threadIdx.x;
    const int ITEMS = (NN + 1023) / 1024;
    int base = t * ITEMS;
    int s = 0;
    for (int i = 0; i < ITEMS; i++) {
        int idx = base + i;
        if (idx < NN) s += g_deg[idx];
    }
    sh[t] = s;
    __syncthreads();
    for (int off = 1; off < 1024; off <<= 1) {
        int v = (t >= off) ? sh[t - off] : 0;
        __syncthreads();
        sh[t] += v;
        __syncthreads();
    }
    int run = sh[t] - s;
    for (int i = 0; i < ITEMS; i++) {
        int idx = base + i;
        if (idx < NN) {
            g_rowptr[idx] = run;
            g_wptr[idx]   = run;
            run += g_deg[idx];
        }
    }
    if (t == 0) g_rowptr[NN] = EE;
}

__global__ void scatter_kernel(const int* __restrict__ src, const int* __restrict__ dst) {
    int i = blockIdx.x*blockDim.x + threadIdx.x;
    if (i < EE) {
        int d = dst[i];
        int p = atomicAdd(&g_wptr[d], 1);
        g_srcs[p] = src[i];
    }
}

// ------------- tf32x3 tensor-core GEMM, pre-split fragment smem ----------
// AMODE 0: A from g_afrag (pure copy). AMODE 1: A float rows, in-kernel split.
// B always from g_wf[wfoff]. C(MxNcols)=A@B [+bias][+leaky 0.01].
// al != nullptr: attention dots for head hh=blockIdx.x -> g_el/g_er.
template<int AMODE>
__global__ __launch_bounds__(256, 2)
void tf32gemm_kernel(const float* __restrict__ A, int wfoff,
                     const float* __restrict__ bias, float* __restrict__ C,
                     int M, int Ncols, int act,
                     const float* __restrict__ al, const float* __restrict__ ar)
{
    __shared__ __align__(16) uint32_t As[16*264];   // blk*264 + plane*132 + L*4 + reg
    __shared__ __align__(16) uint32_t Bs[4096];     // ((ks*2+wn)*8+nt)*128 + L*4 + w
    __shared__ float sEl[2][128], sEr[2][128];

    int tid  = threadIdx.x;
    int lane = tid & 31, warp = tid >> 5;
    int wm = warp >> 1, wn = warp & 1;
    int mblk = blockIdx.y, cb = blockIdx.x;
    int m0 = mblk*128, col0 = cb*128;

    float acc[2][8][4];
    #pragma unroll
    for (int i = 0; i < 2; i++)
        #pragma unroll
        for (int j = 0; j < 8; j++)
            #pragma unroll
            for (int q = 0; q < 4; q++) acc[i][j][q] = 0.f;

    const uint32_t* wf = &g_wf[wfoff + cb*32768];
    const uint32_t* af = &g_afrag[mblk*32768];

    uint4 bpr[4];
    uint4 apr[4];
    float4 a0, a1;
    const float4 z4 = make_float4(0.f,0.f,0.f,0.f);

    // prefetch chunk 0
    #pragma unroll
    for (int i = 0; i < 4; i++)
        bpr[i] = *(const uint4*)&wf[i*1024 + tid*4];
    if (AMODE == 0) {
        #pragma unroll
        for (int i = 0; i < 4; i++)
            apr[i] = *(const uint4*)&af[i*1024 + tid*4];
    } else {
        int gr = m0 + (tid >> 1);
        const float* ap = &A[(size_t)gr*128 + (tid & 1)*8];
        a0 = (gr < M) ? *(const float4*)ap       : z4;
        a1 = (gr < M) ? *(const float4*)(ap + 4) : z4;
    }

    #pragma unroll 1
    for (int ch = 0; ch < 8; ch++) {
        if (ch) __syncthreads();
        // ---- store B (pure copy) ----
        #pragma unroll
        for (int i = 0; i < 4; i++)
            *(uint4*)&Bs[i*1024 + tid*4] = bpr[i];
        // ---- store A ----
        if (AMODE == 0) {
            #pragma unroll
            for (int i = 0; i < 4; i++) {
                int w = i*1024 + tid*4;
                int blk = w >> 8, rem = w & 255;
                *(uint4*)&As[blk*264 + (rem >> 7)*132 + (rem & 127)] = apr[i];
            }
        } else {
            int am = tid >> 1, akh = tid & 1;
            int mtile = am >> 4, r16 = am & 15;
            int base = (mtile*2 + akh)*264;
            float v[8] = {a0.x,a0.y,a0.z,a0.w, a1.x,a1.y,a1.z,a1.w};
            #pragma unroll
            for (int e = 0; e < 8; e++) {
                uint32_t hi = cvt_tf32(v[e]);
                uint32_t lo = cvt_tf32(v[e] - __uint_as_float(hi));
                int off = ((r16 & 7)*4 + (e & 3))*4 + (e >> 2)*2 + (r16 >> 3);
                As[base + off]       = hi;
                As[base + 132 + off] = lo;
            }
        }
        __syncthreads();
        if (ch < 7) {   // prefetch next chunk (overlaps mma)
            #pragma unroll
            for (int i = 0; i < 4; i++)
                bpr[i] = *(const uint4*)&wf[(ch+1)*4096 + i*1024 + tid*4];
            if (AMODE == 0) {
                #pragma unroll
                for (int i = 0; i < 4; i++)
                    apr[i] = *(const uint4*)&af[(ch+1)*4096 + i*1024 + tid*4];
            } else {
                int gr = m0 + (tid >> 1);
                const float* ap = &A[(size_t)gr*128 + (ch+1)*16 + (tid & 1)*8];
                a0 = (gr < M) ? *(const float4*)ap       : z4;
                a1 = (gr < M) ? *(const float4*)(ap + 4) : z4;
            }
        }
        // ---- mma ----
        #pragma unroll
        for (int ks = 0; ks < 2; ks++) {
            uint4 ah[2], alo[2];
            #pragma unroll
            for (int mt = 0; mt < 2; mt++) {
                int blk = (wm*2 + mt)*2 + ks;
                ah[mt]  = *(const uint4*)&As[blk*264 + lane*4];
                alo[mt] = *(const uint4*)&As[blk*264 + 132 + lane*4];
            }
            #pragma unroll
            for (int nt = 0; nt < 8; nt++) {
                uint4 bq = *(const uint4*)&Bs[((ks*2 + wn)*8 + nt)*128 + lane*4];
                #pragma unroll
                for (int mt = 0; mt < 2; mt++) {
                    mma8(acc[mt][nt], (const uint32_t*)&ah[mt],  bq.x, bq.y);
                    mma8(acc[mt][nt], (const uint32_t*)&ah[mt],  bq.z, bq.w);
                    mma8(acc[mt][nt], (const uint32_t*)&alo[mt], bq.x, bq.y);
                }
            }
        }
    }

    // ---------------- epilogue: store C ----------------------------------
    #pragma unroll
    for (int mt = 0; mt < 2; mt++) {
        #pragma unroll
        for (int half = 0; half < 2; half++) {
            int r = m0 + wm*32 + mt*16 + (lane >> 2) + half*8;
            if (r >= M) continue;
            #pragma unroll
            for (int nt = 0; nt < 8; nt++) {
                int c = col0 + wn*64 + nt*8 + 2*(lane & 3);
                float v0 = acc[mt][nt][half*2 + 0];
                float v1 = acc[mt][nt][half*2 + 1];
                if (bias) { v0 += bias[c]; v1 += bias[c+1]; }
                if (act)  { v0 = v0 > 0.f ? v0 : 0.01f*v0;
                            v1 = v1 > 0.f ? v1 : 0.01f*v1; }
                *(float2*)&C[(size_t)r*Ncols + c] = make_float2(v0, v1);
            }
        }
    }

    // ---------------- fused attention dots (GAT path) --------------------
    if (al) {
        int hh = blockIdx.x;
        float alv[8][2], arv[8][2];
        #pragma unroll
        for (int nt = 0; nt < 8; nt++)
            #pragma unroll
            for (int j = 0; j < 2; j++) {
                int c = wn*64 + nt*8 + 2*(lane & 3) + j;
                alv[nt][j] = __ldg(&al[hh*HIDN + c]);
                arv[nt][j] = __ldg(&ar[hh*HIDN + c]);
            }
        #pragma unroll
        for (int mt = 0; mt < 2; mt++) {
            #pragma unroll
            for (int half = 0; half < 2; half++) {
                float pl = 0.f, pr = 0.f;
                #pragma unroll
                for (int nt = 0; nt < 8; nt++)
                    #pragma unroll
                    for (int j = 0; j < 2; j++) {
                        float v = acc[mt][nt][half*2 + j];
                        pl += v * alv[nt][j];
                        pr += v * arv[nt][j];
                    }
                pl += __shfl_xor_sync(0xffffffffu, pl, 1);
                pl += __shfl_xor_sync(0xffffffffu, pl, 2);
                pr += __shfl_xor_sync(0xffffffffu, pr, 1);
                pr += __shfl_xor_sync(0xffffffffu, pr, 2);
                if ((lane & 3) == 0) {
                    int rl = wm*32 + mt*16 + (lane >> 2) + half*8;
                    sEl[wn][rl] = pl;
                    sEr[wn][rl] = pr;
                }
            }
        }
        __syncthreads();
        if (tid < 128) {
            int r = m0 + tid;
            if (r < M) {
                g_el[r*HH + hh] = sEl[0][tid] + sEl[1][tid];
                g_er[r*HH + hh] = sEr[0][tid] + sEr[1][tid];
            }
        }
    }
}

// ---------------- fused edge logits + softmax, warp per (dst,head) -------
__global__ void edge_softmax_kernel()
{
    int gw   = (blockIdx.x*blockDim.x + threadIdx.x) >> 5;
    int lane = threadIdx.x & 31;
    if (gw >= NN*HH) return;
    int n = gw / HH, hh = gw % HH;
    int beg = g_rowptr[n], end = g_rowptr[n+1];
    if (beg == end) return;
    float er_n = g_er[n*HH + hh];
    float* ap = &g_alpha[hh*EE];
    float mx = -1e30f;
    for (int j = beg + lane; j < end; j += 32) {
        int s = g_srcs[j];
        float v = g_el[s*HH + hh] + er_n;
        v = v > 0.f ? v : 0.2f*v;
        ap[j] = v;
        mx = fmaxf(mx, v);
    }
    #pragma unroll
    for (int o = 16; o; o >>= 1) mx = fmaxf(mx, __shfl_xor_sync(0xffffffffu, mx, o));
    float s = 0.f;
    for (int j = beg + lane; j < end; j += 32) {
        float e = expf(ap[j] - mx);
        ap[j] = e;
        s += e;
    }
    #pragma unroll
    for (int o = 16; o; o >>= 1) s += __shfl_xor_sync(0xffffffffu, s, o);
    if (lane == 0) g_dnm[n*HH + hh] = 1.f / (s + 1e-9f);
}

// ------ aggregation: warp per head, float4 per lane, head-mean -> g_x ----
// writeFrag: also emit A-fragment hi/lo planes for the next GAT GEMM.
__global__ __launch_bounds__(96)
void aggregate_kernel(const float* __restrict__ bias, int writeFrag)
{
    __shared__ float4 sh[3][32];
    int n = blockIdx.x;
    int t = threadIdx.x;
    int head = t >> 5, lane = t & 31;
    int beg = g_rowptr[n], end = g_rowptr[n+1];

    const float* hb = &g_h[(size_t)head*HIDN + lane*4];
    const float* wp = &g_alpha[head*EE];

    float4 a = make_float4(0.f, 0.f, 0.f, 0.f);
    int j = beg;
    if (j + 1 < end) {
        int   s0 = g_srcs[j],   s1 = g_srcs[j+1];
        float w0 = __ldg(&wp[j]), w1 = __ldg(&wp[j+1]);
        for (; j + 3 < end; j += 2) {
            int   ns0 = g_srcs[j+2],   ns1 = g_srcs[j+3];
            float nw0 = __ldg(&wp[j+2]), nw1 = __ldg(&wp[j+3]);
            float4 v0 = *(const float4*)&hb[(size_t)s0*HF];
            float4 v1 = *(const float4*)&hb[(size_t)s1*HF];
            a.x += w0*v0.x + w1*v1.x;
            a.y += w0*v0.y + w1*v1.y;
            a.z += w0*v0.z + w1*v1.z;
            a.w += w0*v0.w + w1*v1.w;
            s0 = ns0; s1 = ns1; w0 = nw0; w1 = nw1;
        }
        float4 v0 = *(const float4*)&hb[(size_t)s0*HF];
        float4 v1 = *(const float4*)&hb[(size_t)s1*HF];
        a.x += w0*v0.x + w1*v1.x;
        a.y += w0*v0.y + w1*v1.y;
        a.z += w0*v0.z + w1*v1.z;
        a.w += w0*v0.w + w1*v1.w;
        j += 2;
    }
    for (; j < end; j++) {
        int s = g_srcs[j];
        float w = __ldg(&wp[j]);
        float4 v = *(const float4*)&hb[(size_t)s*HF];
        a.x += w*v.x; a.y += w*v.y; a.z += w*v.z; a.w += w*v.w;
    }

    float dnm = g_dnm[n*HH + head];
    const float4 b4 = *(const float4*)&bias[head*HIDN + lane*4];
    a.x = a.x*dnm + b4.x;  a.y = a.y*dnm + b4.y;
    a.z = a.z*dnm + b4.z;  a.w = a.w*dnm + b4.w;
    a.x = a.x > 0.f ? a.x : 0.01f*a.x;
    a.y = a.y > 0.f ? a.y : 0.01f*a.y;
    a.z = a.z > 0.f ? a.z : 0.01f*a.z;
    a.w = a.w > 0.f ? a.w : 0.01f*a.w;
    sh[head][lane] = a;
    __syncthreads();
    if (t < 32) {
        float4 r0 = sh[0][t], r1 = sh[1][t], r2 = sh[2][t];
        float o[4];
        o[0] = (r0.x + r1.x + r2.x) * (1.f/3.f);
        o[1] = (r0.y + r1.y + r2.y) * (1.f/3.f);
        o[2] = (r0.z + r1.z + r2.z) * (1.f/3.f);
        o[3] = (r0.w + r1.w + r2.w) * (1.f/3.f);
        *(float4*)&g_x[(size_t)n*HIDN + t*4] = make_float4(o[0],o[1],o[2],o[3]);
        if (writeFrag) {
            #pragma unroll
            for (int f = 0; f < 4; f++) {
                uint32_t hi = cvt_tf32(o[f]);
                uint32_t lo = cvt_tf32(o[f] - __uint_as_float(hi));
                int ad = frag_addr(n, t*4 + f);
                g_afrag[ad]       = hi;
                g_afrag[ad + 128] = lo;
            }
        }
    }
}

// ---------------- classifier: (N,128)@(128,6)+b, warp per node -----------
__global__ void classifier_kernel(const float* __restrict__ lw5, const float* __restrict__ lb5,
                                  float* __restrict__ out)
{
    int gw   = (blockIdx.x*blockDim.x + threadIdx.x) >> 5;
    int lane = threadIdx.x & 31;
    if (gw >= NN) return;
    const float* xr = &g_x[(size_t)gw*HIDN];
    float acc[NCLS] = {};
    #pragma unroll
    for (int k = lane; k < HIDN; k += 32) {
        float xv = xr[k];
        #pragma unroll
        for (int c = 0; c < NCLS; c++) acc[c] += xv * __ldg(&lw5[k*NCLS + c]);
    }
    #pragma unroll
    for (int c = 0; c < NCLS; c++)
        #pragma unroll
        for (int o = 16; o; o >>= 1) acc[c] += __shfl_xor_sync(0xffffffffu, acc[c], o);
    if (lane == 0) {
        #pragma unroll
        for (int c = 0; c < NCLS; c++) out[gw*NCLS + c] = acc[c] + lb5[c];
    }
}

// -------------------------------------------------------------------------
extern "C" void kernel_launch(void* const* d_in, const int* in_sizes, int n_in,
                              void* d_out, int out_size)
{
    const float* in_feat = (const float*)d_in[0];
    const int*   src     = (const int*)  d_in[1];
    const int*   dst     = (const int*)  d_in[2];
    const float* W1  = (const float*)d_in[3];
    const float* al1 = (const float*)d_in[4];
    const float* ar1 = (const float*)d_in[5];
    const float* b1  = (const float*)d_in[6];
    const float* W2  = (const float*)d_in[7];
    const float* al2 = (const float*)d_in[8];
    const float* ar2 = (const float*)d_in[9];
    const float* b2  = (const float*)d_in[10];
    const float* lw1 = (const float*)d_in[11];
    const float* lb1 = (const float*)d_in[12];
    const float* lw2 = (const float*)d_in[13];
    const float* lb2 = (const float*)d_in[14];
    const float* lw3 = (const float*)d_in[15];
    const float* lb3 = (const float*)d_in[16];
    const float* lw4 = (const float*)d_in[17];
    const float* lb4 = (const float*)d_in[18];
    const float* lw5 = (const float*)d_in[19];
    const float* lb5 = (const float*)d_in[20];
    float* out = (float*)d_out;

    float *ph, *px, *py;
    cudaGetSymbolAddress((void**)&ph, g_h);
    cudaGetSymbolAddress((void**)&px, g_x);
    cudaGetSymbolAddress((void**)&py, g_y);

    const int TB = 256;
    int warp_blocks = (NN*HH + 7) / 8;

    dim3 g_gat(HF/128, MBLKS);     // (3, 391)
    dim3 g_mlp(1, MBLKS);

    // pre-splits first (also positions gemm1 as the ncu-captured launch)
    presplit_w_kernel<<<(163840 + TB - 1)/TB, TB>>>(W1, W2, lw1, lw2, lw3, lw4);
    presplit_a_kernel<<<(MBLKS*128*128 + TB - 1)/TB, TB>>>(in_feat);
    zero_deg_kernel<<<(NN + TB - 1)/TB, TB>>>();

    // ---- GAT layer 1 GEMM (independent of CSR build) ----
    tf32gemm_kernel<0><<<g_gat, 256>>>(nullptr, WF_W1, nullptr, ph, NN, HF, 0, al1, ar1);

    // CSR build
    hist_kernel<<<(EE + TB - 1)/TB, TB>>>(dst);
    scan_kernel<<<1, 1024>>>();
    scatter_kernel<<<(EE + TB - 1)/TB, TB>>>(src, dst);

    // ---- GAT layer 1 edge phase ----
    edge_softmax_kernel<<<warp_blocks, 256>>>();
    aggregate_kernel<<<NN, 96>>>(b1, 1);   // writes g_x + g_afrag

    // ---- GAT layer 2 ----
    tf32gemm_kernel<0><<<g_gat, 256>>>(nullptr, WF_W2, nullptr, ph, NN, HF, 0, al2, ar2);
    edge_softmax_kernel<<<warp_blocks, 256>>>();
    aggregate_kernel<<<NN, 96>>>(b2, 0);

    // ---- MLP head ----
    tf32gemm_kernel<1><<<g_mlp, 256>>>(px, WF_L1, lb1, py, NN, HIDN, 1, nullptr, nullptr);
    tf32gemm_kernel<1><<<g_mlp, 256>>>(py, WF_L2, lb2, px, NN, HIDN, 1, nullptr, nullptr);
    tf32gemm_kernel<1><<<g_mlp, 256>>>(px, WF_L3, lb3, py, NN, HIDN, 1, nullptr, nullptr);
    tf32gemm_kernel<1><<<g_mlp, 256>>>(py, WF_L4, lb4, px, NN, HIDN, 1, nullptr, nullptr);
    classifier_kernel<<<(NN + 7)/8, 256>>>(lw5, lb5, out);
}

// round 7
// speedup vs baseline: 1.0383x; 1.0383x over previous
#include <cuda_runtime.h>
#include <cstdint>

#define NN 50000
#define EE 800000
#define HH 3
#define HIDN 128
#define HF (HH*HIDN)   // 384
#define NCLS 6
#define MBLKS 391      // ceil(50000/128)
#define CAP 128        // per-node cached-edge capacity in fused agg kernel

// weight-fragment scratch offsets (words)
#define WF_W1  0
#define WF_W2  98304
#define WF_L1  196608
#define WF_L2  229376
#define WF_L3  262144
#define WF_L4  294912
#define WF_TOT 327680

// ---------------- scratch (device globals; no allocation allowed) --------
__device__ float    g_h[NN*HF];     // post-GEMM per-head features
__device__ float    g_x[NN*HIDN];   // layer input / MLP ping
__device__ float    g_y[NN*HIDN];   // MLP pong
__device__ float    g_el[NN*HH];
__device__ float    g_er[NN*HH];
__device__ int      g_srcs[EE];     // src node id in CSR order
__device__ int      g_deg[NN];
__device__ int      g_rowptr[NN+1];
__device__ int      g_wptr[NN];
__device__ uint32_t g_wf[WF_TOT];           // pre-split weight frags (hi/lo)
__device__ uint32_t g_afrag[MBLKS*8*4096];  // pre-split A frags (hi/lo)

// ---------------- helpers -------------------------------------------------
__device__ __forceinline__ uint32_t cvt_tf32(float f) {
    uint32_t r;
    asm("cvt.rna.tf32.f32 %0, %1;" : "=r"(r) : "f"(f));
    return r;
}
__device__ __forceinline__ void mma8(float* c, const uint32_t* a, uint32_t b0, uint32_t b1) {
    asm("mma.sync.aligned.m16n8k8.row.col.f32.tf32.tf32.f32 "
        "{%0,%1,%2,%3}, {%4,%5,%6,%7}, {%8,%9}, {%0,%1,%2,%3};"
        : "+f"(c[0]), "+f"(c[1]), "+f"(c[2]), "+f"(c[3])
        : "r"(a[0]), "r"(a[1]), "r"(a[2]), "r"(a[3]), "r"(b0), "r"(b1));
}
// packed A-frag address for element (row, k); hi word; lo at +128
__device__ __forceinline__ int frag_addr(int row, int k) {
    int mblk = row >> 7, mtile = (row >> 4) & 7, r16 = row & 15;
    int ch = k >> 4, ks = (k >> 3) & 1, k8 = k & 7;
    int blk = mtile*2 + ks;
    int L   = (r16 & 7)*4 + (k8 & 3);
    int reg = (k8 >> 2)*2 + (r16 >> 3);
    return (((mblk*8 + ch)*16 + blk) << 8) + (L << 2) + reg;
}

// ---------------- pre-split kernels --------------------------------------
__global__ void presplit_w_kernel(const float* __restrict__ W1, const float* __restrict__ W2,
                                  const float* __restrict__ L1, const float* __restrict__ L2,
                                  const float* __restrict__ L3, const float* __restrict__ L4)
{
    int i = blockIdx.x*blockDim.x + threadIdx.x;
    if (i >= 163840) return;
    const float* W; int ncols, ooff, rem;
    if      (i < 49152)  { W = W1; ncols = 384; ooff = WF_W1; rem = i; }
    else if (i < 98304)  { W = W2; ncols = 384; ooff = WF_W2; rem = i - 49152; }
    else if (i < 114688) { W = L1; ncols = 128; ooff = WF_L1; rem = i - 98304; }
    else if (i < 131072) { W = L2; ncols = 128; ooff = WF_L2; rem = i - 114688; }
    else if (i < 147456) { W = L3; ncols = 128; ooff = WF_L3; rem = i - 131072; }
    else                 { W = L4; ncols = 128; ooff = WF_L4; rem = i - 147456; }
    int g = rem >> 6, idx = rem & 63;
    int L = idx >> 1, kb = idx & 1;
    int nt = g & 7, wn = (g >> 3) & 1, ks = (g >> 4) & 1, ch = (g >> 5) & 7, cb = g >> 8;
    int k = ch*16 + ks*8 + (L & 3) + kb*4;
    int n = cb*128 + wn*64 + nt*8 + (L >> 2);
    float v = W[k*ncols + n];
    uint32_t hi = cvt_tf32(v);
    uint32_t lo = cvt_tf32(v - __uint_as_float(hi));
    g_wf[ooff + g*128 + L*4 + kb]     = hi;
    g_wf[ooff + g*128 + L*4 + 2 + kb] = lo;
}

__global__ void presplit_a_kernel(const float* __restrict__ X)
{
    int i = blockIdx.x*blockDim.x + threadIdx.x;
    if (i >= MBLKS*128*128) return;
    int row = i >> 7, k = i & 127;
    float v = (row < NN) ? X[row*128 + k] : 0.f;
    uint32_t hi = cvt_tf32(v);
    uint32_t lo = cvt_tf32(v - __uint_as_float(hi));
    int a = frag_addr(row, k);
    g_afrag[a]       = hi;
    g_afrag[a + 128] = lo;
}

// ---------------- CSR build ----------------------------------------------
__global__ void zero_deg_kernel() {
    int i = blockIdx.x*blockDim.x + threadIdx.x;
    if (i < NN) g_deg[i] = 0;
}

__global__ void hist_kernel(const int* __restrict__ dst) {
    int i = blockIdx.x*blockDim.x + threadIdx.x;
    if (i < EE) atomicAdd(&g_deg[dst[i]], 1);
}

__global__ void scan_kernel() {
    __shared__ int sh[1024];
    int t = threadIdx.x;
    const int ITEMS = (NN + 1023) / 1024;
    int base = t * ITEMS;
    int s = 0;
    for (int i = 0; i < ITEMS; i++) {
        int idx = base + i;
        if (idx < NN) s += g_deg[idx];
    }
    sh[t] = s;
    __syncthreads();
    for (int off = 1; off < 1024; off <<= 1) {
        int v = (t >= off) ? sh[t - off] : 0;
        __syncthreads();
        sh[t] += v;
        __syncthreads();
    }
    int run = sh[t] - s;
    for (int i = 0; i < ITEMS; i++) {
        int idx = base + i;
        if (idx < NN) {
            g_rowptr[idx] = run;
            g_wptr[idx]   = run;
            run += g_deg[idx];
        }
    }
    if (t == 0) g_rowptr[NN] = EE;
}

__global__ void scatter_kernel(const int* __restrict__ src, const int* __restrict__ dst) {
    int i = blockIdx.x*blockDim.x + threadIdx.x;
    if (i < EE) {
        int d = dst[i];
        int p = atomicAdd(&g_wptr[d], 1);
        g_srcs[p] = src[i];
    }
}

// ------------- tf32x3 tensor-core GEMM, pre-split fragment smem ----------
// AMODE 0: A from g_afrag (pure copy). AMODE 1: A float rows, in-kernel split.
// B always from g_wf[wfoff]. C(MxNcols)=A@B [+bias][+leaky 0.01].
// al != nullptr: attention dots for head hh=blockIdx.x -> g_el/g_er.
template<int AMODE>
__global__ __launch_bounds__(256, 2)
void tf32gemm_kernel(const float* __restrict__ A, int wfoff,
                     const float* __restrict__ bias, float* __restrict__ C,
                     int M, int Ncols, int act,
                     const float* __restrict__ al, const float* __restrict__ ar)
{
    __shared__ __align__(16) uint32_t As[16*264];   // blk*264 + plane*132 + L*4 + reg
    __shared__ __align__(16) uint32_t Bs[4096];     // ((ks*2+wn)*8+nt)*128 + L*4 + w
    __shared__ float sEl[2][128], sEr[2][128];

    int tid  = threadIdx.x;
    int lane = tid & 31, warp = tid >> 5;
    int wm = warp >> 1, wn = warp & 1;
    int mblk = blockIdx.y, cb = blockIdx.x;
    int m0 = mblk*128, col0 = cb*128;

    float acc[2][8][4];
    #pragma unroll
    for (int i = 0; i < 2; i++)
        #pragma unroll
        for (int j = 0; j < 8; j++)
            #pragma unroll
            for (int q = 0; q < 4; q++) acc[i][j][q] = 0.f;

    const uint32_t* wf = &g_wf[wfoff + cb*32768];
    const uint32_t* af = &g_afrag[mblk*32768];

    uint4 bpr[4];
    uint4 apr[4];
    float4 a0, a1;
    const float4 z4 = make_float4(0.f,0.f,0.f,0.f);

    // prefetch chunk 0
    #pragma unroll
    for (int i = 0; i < 4; i++)
        bpr[i] = *(const uint4*)&wf[i*1024 + tid*4];
    if (AMODE == 0) {
        #pragma unroll
        for (int i = 0; i < 4; i++)
            apr[i] = *(const uint4*)&af[i*1024 + tid*4];
    } else {
        int gr = m0 + (tid >> 1);
        const float* ap = &A[(size_t)gr*128 + (tid & 1)*8];
        a0 = (gr < M) ? *(const float4*)ap       : z4;
        a1 = (gr < M) ? *(const float4*)(ap + 4) : z4;
    }

    #pragma unroll 1
    for (int ch = 0; ch < 8; ch++) {
        if (ch) __syncthreads();
        // ---- store B (pure copy) ----
        #pragma unroll
        for (int i = 0; i < 4; i++)
            *(uint4*)&Bs[i*1024 + tid*4] = bpr[i];
        // ---- store A ----
        if (AMODE == 0) {
            #pragma unroll
            for (int i = 0; i < 4; i++) {
                int w = i*1024 + tid*4;
                int blk = w >> 8, rem = w & 255;
                *(uint4*)&As[blk*264 + (rem >> 7)*132 + (rem & 127)] = apr[i];
            }
        } else {
            int am = tid >> 1, akh = tid & 1;
            int mtile = am >> 4, r16 = am & 15;
            int base = (mtile*2 + akh)*264;
            float v[8] = {a0.x,a0.y,a0.z,a0.w, a1.x,a1.y,a1.z,a1.w};
            #pragma unroll
            for (int e = 0; e < 8; e++) {
                uint32_t hi = cvt_tf32(v[e]);
                uint32_t lo = cvt_tf32(v[e] - __uint_as_float(hi));
                int off = ((r16 & 7)*4 + (e & 3))*4 + (e >> 2)*2 + (r16 >> 3);
                As[base + off]       = hi;
                As[base + 132 + off] = lo;
            }
        }
        __syncthreads();
        if (ch < 7) {   // prefetch next chunk (overlaps mma)
            #pragma unroll
            for (int i = 0; i < 4; i++)
                bpr[i] = *(const uint4*)&wf[(ch+1)*4096 + i*1024 + tid*4];
            if (AMODE == 0) {
                #pragma unroll
                for (int i = 0; i < 4; i++)
                    apr[i] = *(const uint4*)&af[(ch+1)*4096 + i*1024 + tid*4];
            } else {
                int gr = m0 + (tid >> 1);
                const float* ap = &A[(size_t)gr*128 + (ch+1)*16 + (tid & 1)*8];
                a0 = (gr < M) ? *(const float4*)ap       : z4;
                a1 = (gr < M) ? *(const float4*)(ap + 4) : z4;
            }
        }
        // ---- mma: nt pairs live -> RAW distance 4 on each accumulator ----
        #pragma unroll
        for (int ks = 0; ks < 2; ks++) {
            uint4 ah[2], alo[2];
            #pragma unroll
            for (int mt = 0; mt < 2; mt++) {
                int blk = (wm*2 + mt)*2 + ks;
                ah[mt]  = *(const uint4*)&As[blk*264 + lane*4];
                alo[mt] = *(const uint4*)&As[blk*264 + 132 + lane*4];
            }
            #pragma unroll
            for (int ng = 0; ng < 4; ng++) {
                int nA = 2*ng, nB = 2*ng + 1;
                uint4 b0 = *(const uint4*)&Bs[((ks*2 + wn)*8 + nA)*128 + lane*4];
                uint4 b1 = *(const uint4*)&Bs[((ks*2 + wn)*8 + nB)*128 + lane*4];
                // term 1: Ahi * Bhi
                mma8(acc[0][nA], (const uint32_t*)&ah[0],  b0.x, b0.y);
                mma8(acc[1][nA], (const uint32_t*)&ah[1],  b0.x, b0.y);
                mma8(acc[0][nB], (const uint32_t*)&ah[0],  b1.x, b1.y);
                mma8(acc[1][nB], (const uint32_t*)&ah[1],  b1.x, b1.y);
                // term 2: Ahi * Blo
                mma8(acc[0][nA], (const uint32_t*)&ah[0],  b0.z, b0.w);
                mma8(acc[1][nA], (const uint32_t*)&ah[1],  b0.z, b0.w);
                mma8(acc[0][nB], (const uint32_t*)&ah[0],  b1.z, b1.w);
                mma8(acc[1][nB], (const uint32_t*)&ah[1],  b1.z, b1.w);
                // term 3: Alo * Bhi
                mma8(acc[0][nA], (const uint32_t*)&alo[0], b0.x, b0.y);
                mma8(acc[1][nA], (const uint32_t*)&alo[1], b0.x, b0.y);
                mma8(acc[0][nB], (const uint32_t*)&alo[0], b1.x, b1.y);
                mma8(acc[1][nB], (const uint32_t*)&alo[1], b1.x, b1.y);
            }
        }
    }

    // ---------------- epilogue: store C ----------------------------------
    #pragma unroll
    for (int mt = 0; mt < 2; mt++) {
        #pragma unroll
        for (int half = 0; half < 2; half++) {
            int r = m0 + wm*32 + mt*16 + (lane >> 2) + half*8;
            if (r >= M) continue;
            #pragma unroll
            for (int nt = 0; nt < 8; nt++) {
                int c = col0 + wn*64 + nt*8 + 2*(lane & 3);
                float v0 = acc[mt][nt][half*2 + 0];
                float v1 = acc[mt][nt][half*2 + 1];
                if (bias) { v0 += bias[c]; v1 += bias[c+1]; }
                if (act)  { v0 = v0 > 0.f ? v0 : 0.01f*v0;
                            v1 = v1 > 0.f ? v1 : 0.01f*v1; }
                *(float2*)&C[(size_t)r*Ncols + c] = make_float2(v0, v1);
            }
        }
    }

    // ---------------- fused attention dots (GAT path) --------------------
    if (al) {
        int hh = blockIdx.x;
        float alv[8][2], arv[8][2];
        #pragma unroll
        for (int nt = 0; nt < 8; nt++)
            #pragma unroll
            for (int j = 0; j < 2; j++) {
                int c = wn*64 + nt*8 + 2*(lane & 3) + j;
                alv[nt][j] = __ldg(&al[hh*HIDN + c]);
                arv[nt][j] = __ldg(&ar[hh*HIDN + c]);
            }
        #pragma unroll
        for (int mt = 0; mt < 2; mt++) {
            #pragma unroll
            for (int half = 0; half < 2; half++) {
                float pl = 0.f, pr = 0.f;
                #pragma unroll
                for (int nt = 0; nt < 8; nt++)
                    #pragma unroll
                    for (int j = 0; j < 2; j++) {
                        float v = acc[mt][nt][half*2 + j];
                        pl += v * alv[nt][j];
                        pr += v * arv[nt][j];
                    }
                pl += __shfl_xor_sync(0xffffffffu, pl, 1);
                pl += __shfl_xor_sync(0xffffffffu, pl, 2);
                pr += __shfl_xor_sync(0xffffffffu, pr, 1);
                pr += __shfl_xor_sync(0xffffffffu, pr, 2);
                if ((lane & 3) == 0) {
                    int rl = wm*32 + mt*16 + (lane >> 2) + half*8;
                    sEl[wn][rl] = pl;
                    sEr[wn][rl] = pr;
                }
            }
        }
        __syncthreads();
        if (tid < 128) {
            int r = m0 + tid;
            if (r < M) {
                g_el[r*HH + hh] = sEl[0][tid] + sEl[1][tid];
                g_er[r*HH + hh] = sEr[0][tid] + sEr[1][tid];
            }
        }
    }
}

// ---- fused softmax + aggregation, block (96 thr) per node ---------------
// Warp = head. Phase A: edge logits + max + exp-sum (smem-cached, with
// recompute fallback past CAP). Phase B: alpha-weighted gather of h[src].
// Epilogue: inv-denom, bias, leaky(0.01), head-mean -> g_x [+ A frags].
__global__ __launch_bounds__(96)
void agg_kernel(const float* __restrict__ bias, int writeFrag)
{
    __shared__ int    sSrc[CAP];
    __shared__ float  sE[3][CAP];
    __shared__ float4 sh4[3][32];
    int n = blockIdx.x;
    int t = threadIdx.x, head = t >> 5, lane = t & 31;
    int beg = g_rowptr[n], end = g_rowptr[n+1];
    int deg = end - beg;
    int cached = deg < CAP ? deg : CAP;
    for (int j = t; j < cached; j += 96) sSrc[j] = g_srcs[beg + j];
    __syncthreads();

    float er_n = g_er[n*HH + head];
    // pass 1: logits + running max
    float mx = -1e30f;
    for (int j = lane; j < deg; j += 32) {
        int s = (j < CAP) ? sSrc[j] : g_srcs[beg + j];
        float v = g_el[s*HH + head] + er_n;
        v = v > 0.f ? v : 0.2f*v;
        if (j < CAP) sE[head][j] = v;
        mx = fmaxf(mx, v);
    }
    #pragma unroll
    for (int o = 16; o; o >>= 1) mx = fmaxf(mx, __shfl_xor_sync(0xffffffffu, mx, o));
    // pass 2: exp + sum
    float sum = 0.f;
    for (int j = lane; j < deg; j += 32) {
        float v;
        if (j < CAP) v = sE[head][j];
        else {
            int s = g_srcs[beg + j];
            v = g_el[s*HH + head] + er_n;
            v = v > 0.f ? v : 0.2f*v;
        }
        float e = expf(v - mx);
        if (j < CAP) sE[head][j] = e;
        sum += e;
    }
    #pragma unroll
    for (int o = 16; o; o >>= 1) sum += __shfl_xor_sync(0xffffffffu, sum, o);
    float inv = 1.f / (sum + 1e-9f);
    __syncwarp();

    // phase B: weighted gather, 2x unrolled
    const float* hb = &g_h[(size_t)head*HIDN + lane*4];
    float4 a = make_float4(0.f, 0.f, 0.f, 0.f);
    int j = beg;
    int jn = 0;
    for (; jn + 1 < cached; jn += 2) {
        int   s0 = sSrc[jn],      s1 = sSrc[jn+1];
        float w0 = sE[head][jn],  w1 = sE[head][jn+1];
        float4 v0 = *(const float4*)&hb[(size_t)s0*HF];
        float4 v1 = *(const float4*)&hb[(size_t)s1*HF];
        a.x += w0*v0.x + w1*v1.x;
        a.y += w0*v0.y + w1*v1.y;
        a.z += w0*v0.z + w1*v1.z;
        a.w += w0*v0.w + w1*v1.w;
    }
    for (; jn < cached; jn++) {
        int s = sSrc[jn];
        float w = sE[head][jn];
        float4 v = *(const float4*)&hb[(size_t)s*HF];
        a.x += w*v.x; a.y += w*v.y; a.z += w*v.z; a.w += w*v.w;
    }
    for (j = beg + CAP; j < end; j++) {      // rare fallback
        int s = g_srcs[j];
        float v = g_el[s*HH + head] + er_n;
        v = v > 0.f ? v : 0.2f*v;
        float w = expf(v - mx);
        float4 v4 = *(const float4*)&hb[(size_t)s*HF];
        a.x += w*v4.x; a.y += w*v4.y; a.z += w*v4.z; a.w += w*v4.w;
    }

    const float4 b4 = *(const float4*)&bias[head*HIDN + lane*4];
    a.x = a.x*inv + b4.x;  a.y = a.y*inv + b4.y;
    a.z = a.z*inv + b4.z;  a.w = a.w*inv + b4.w;
    a.x = a.x > 0.f ? a.x : 0.01f*a.x;
    a.y = a.y > 0.f ? a.y : 0.01f*a.y;
    a.z = a.z > 0.f ? a.z : 0.01f*a.z;
    a.w = a.w > 0.f ? a.w : 0.01f*a.w;
    sh4[head][lane] = a;
    __syncthreads();
    if (t < 32) {
        float4 r0 = sh4[0][t], r1 = sh4[1][t], r2 = sh4[2][t];
        float o[4];
        o[0] = (r0.x + r1.x + r2.x) * (1.f/3.f);
        o[1] = (r0.y + r1.y + r2.y) * (1.f/3.f);
        o[2] = (r0.z + r1.z + r2.z) * (1.f/3.f);
        o[3] = (r0.w + r1.w + r2.w) * (1.f/3.f);
        *(float4*)&g_x[(size_t)n*HIDN + t*4] = make_float4(o[0],o[1],o[2],o[3]);
        if (writeFrag) {
            #pragma unroll
            for (int f = 0; f < 4; f++) {
                uint32_t hi = cvt_tf32(o[f]);
                uint32_t lo = cvt_tf32(o[f] - __uint_as_float(hi));
                int ad = frag_addr(n, t*4 + f);
                g_afrag[ad]       = hi;
                g_afrag[ad + 128] = lo;
            }
        }
    }
}

// ---------------- classifier: (N,128)@(128,6)+b, warp per node -----------
__global__ void classifier_kernel(const float* __restrict__ lw5, const float* __restrict__ lb5,
                                  float* __restrict__ out)
{
    int gw   = (blockIdx.x*blockDim.x + threadIdx.x) >> 5;
    int lane = threadIdx.x & 31;
    if (gw >= NN) return;
    const float* xr = &g_x[(size_t)gw*HIDN];
    float acc[NCLS] = {};
    #pragma unroll
    for (int k = lane; k < HIDN; k += 32) {
        float xv = xr[k];
        #pragma unroll
        for (int c = 0; c < NCLS; c++) acc[c] += xv * __ldg(&lw5[k*NCLS + c]);
    }
    #pragma unroll
    for (int c = 0; c < NCLS; c++)
        #pragma unroll
        for (int o = 16; o; o >>= 1) acc[c] += __shfl_xor_sync(0xffffffffu, acc[c], o);
    if (lane == 0) {
        #pragma unroll
        for (int c = 0; c < NCLS; c++) out[gw*NCLS + c] = acc[c] + lb5[c];
    }
}

// -------------------------------------------------------------------------
extern "C" void kernel_launch(void* const* d_in, const int* in_sizes, int n_in,
                              void* d_out, int out_size)
{
    const float* in_feat = (const float*)d_in[0];
    const int*   src     = (const int*)  d_in[1];
    const int*   dst     = (const int*)  d_in[2];
    const float* W1  = (const float*)d_in[3];
    const float* al1 = (const float*)d_in[4];
    const float* ar1 = (const float*)d_in[5];
    const float* b1  = (const float*)d_in[6];
    const float* W2  = (const float*)d_in[7];
    const float* al2 = (const float*)d_in[8];
    const float* ar2 = (const float*)d_in[9];
    const float* b2  = (const float*)d_in[10];
    const float* lw1 = (const float*)d_in[11];
    const float* lb1 = (const float*)d_in[12];
    const float* lw2 = (const float*)d_in[13];
    const float* lb2 = (const float*)d_in[14];
    const float* lw3 = (const float*)d_in[15];
    const float* lb3 = (const float*)d_in[16];
    const float* lw4 = (const float*)d_in[17];
    const float* lb4 = (const float*)d_in[18];
    const float* lw5 = (const float*)d_in[19];
    const float* lb5 = (const float*)d_in[20];
    float* out = (float*)d_out;

    float *ph, *px, *py;
    cudaGetSymbolAddress((void**)&ph, g_h);
    cudaGetSymbolAddress((void**)&px, g_x);
    cudaGetSymbolAddress((void**)&py, g_y);

    const int TB = 256;

    dim3 g_gat(HF/128, MBLKS);     // (3, 391)
    dim3 g_mlp(1, MBLKS);

    // pre-splits first (gemm1 stays the 4th launch for ncu)
    presplit_w_kernel<<<(163840 + TB - 1)/TB, TB>>>(W1, W2, lw1, lw2, lw3, lw4);
    presplit_a_kernel<<<(MBLKS*128*128 + TB - 1)/TB, TB>>>(in_feat);
    zero_deg_kernel<<<(NN + TB - 1)/TB, TB>>>();

    // ---- GAT layer 1 GEMM (independent of CSR build) ----
    tf32gemm_kernel<0><<<g_gat, 256>>>(nullptr, WF_W1, nullptr, ph, NN, HF, 0, al1, ar1);

    // CSR build
    hist_kernel<<<(EE + TB - 1)/TB, TB>>>(dst);
    scan_kernel<<<1, 1024>>>();
    scatter_kernel<<<(EE + TB - 1)/TB, TB>>>(src, dst);

    // ---- GAT layer 1 edge phase (fused softmax + aggregate) ----
    agg_kernel<<<NN, 96>>>(b1, 1);   // writes g_x + g_afrag

    // ---- GAT layer 2 ----
    tf32gemm_kernel<0><<<g_gat, 256>>>(nullptr, WF_W2, nullptr, ph, NN, HF, 0, al2, ar2);
    agg_kernel<<<NN, 96>>>(b2, 0);

    // ---- MLP head ----
    tf32gemm_kernel<1><<<g_mlp, 256>>>(px, WF_L1, lb1, py, NN, HIDN, 1, nullptr, nullptr);
    tf32gemm_kernel<1><<<g_mlp, 256>>>(py, WF_L2, lb2, px, NN, HIDN, 1, nullptr, nullptr);
    tf32gemm_kernel<1><<<g_mlp, 256>>>(px, WF_L3, lb3, py, NN, HIDN, 1, nullptr, nullptr);
    tf32gemm_kernel<1><<<g_mlp, 256>>>(py, WF_L4, lb4, px, NN, HIDN, 1, nullptr, nullptr);
    classifier_kernel<<<(NN + 7)/8, 256>>>(lw5, lb5, out);
}

// round 8
// speedup vs baseline: 1.3461x; 1.2964x over previous
#include <cuda_runtime.h>
#include <cuda_bf16.h>
#include <cstdint>

#define NN 50000
#define EE 800000
#define HH 3
#define HIDN 128
#define HF (HH*HIDN)   // 384
#define NCLS 6
#define MBLKS 391      // ceil(50000/128)
#define CAP 128        // per-node cached-edge capacity in fused agg kernel

// weight-fragment scratch offsets (words); bf16 hi/lo packed 2-per-word
#define WF_W1  0
#define WF_W2  49152
#define WF_L1  98304
#define WF_L2  114688
#define WF_L3  131072
#define WF_L4  147456
#define WF_TOT 163840

// ---------------- scratch (device globals; no allocation allowed) --------
__device__ float    g_h[NN*HF];     // post-GEMM per-head features
__device__ float    g_x[NN*HIDN];   // layer input / MLP ping
__device__ float    g_y[NN*HIDN];   // MLP pong
__device__ float    g_el[NN*HH];
__device__ float    g_er[NN*HH];
__device__ int      g_srcs[EE];     // src node id in CSR order
__device__ int      g_deg[NN];
__device__ int      g_rowptr[NN+1];
__device__ int      g_wptr[NN];
__device__ uint32_t g_wf[WF_TOT];            // pre-split bf16 weight frags
__device__ uint32_t g_afrag[MBLKS*16384];    // pre-split bf16 A frags

// ---------------- helpers -------------------------------------------------
// bf16 hi/lo split of two consecutive elements, packed bf16x2 (low half = e0)
__device__ __forceinline__ uint32_t bfpack2(float e0, float e1, uint32_t& loW) {
    __nv_bfloat16 h0 = __float2bfloat16_rn(e0);
    __nv_bfloat16 h1 = __float2bfloat16_rn(e1);
    float r0 = e0 - __bfloat162float(h0);
    float r1 = e1 - __bfloat162float(h1);
    __nv_bfloat16 l0 = __float2bfloat16_rn(r0);
    __nv_bfloat16 l1 = __float2bfloat16_rn(r1);
    loW = (uint32_t)__bfloat16_as_ushort(l0) | ((uint32_t)__bfloat16_as_ushort(l1) << 16);
    return (uint32_t)__bfloat16_as_ushort(h0) | ((uint32_t)__bfloat16_as_ushort(h1) << 16);
}
__device__ __forceinline__ void mma16(float* c, const uint32_t* a, uint32_t b0, uint32_t b1) {
    asm("mma.sync.aligned.m16n8k16.row.col.f32.bf16.bf16.f32 "
        "{%0,%1,%2,%3}, {%4,%5,%6,%7}, {%8,%9}, {%0,%1,%2,%3};"
        : "+f"(c[0]), "+f"(c[1]), "+f"(c[2]), "+f"(c[3])
        : "r"(a[0]), "r"(a[1]), "r"(a[2]), "r"(a[3]), "r"(b0), "r"(b1));
}
// A-fragment word address (hi plane; lo at +128) for element (row, k even)
__device__ __forceinline__ int frag_addr(int row, int k) {
    int mblk = row >> 7, ch = k >> 4, mtile = (row >> 4) & 7;
    int r16 = row & 15, k16 = k & 15;
    int reg  = (k16 >> 3)*2 + (r16 >> 3);
    int lane = (r16 & 7)*4 + ((k16 >> 1) & 3);
    return ((mblk*8 + ch)*8 + mtile)*256 + lane*4 + reg;
}

// ---------------- pre-split kernels --------------------------------------
// thread ranges: W1 [0,24576) W2 [24576,49152) L1..L4 8192 each
__global__ void presplit_w_kernel(const float* __restrict__ W1, const float* __restrict__ W2,
                                  const float* __restrict__ L1, const float* __restrict__ L2,
                                  const float* __restrict__ L3, const float* __restrict__ L4)
{
    int i = blockIdx.x*blockDim.x + threadIdx.x;
    if (i >= 81920) return;
    const float* W; int ncols, ooff, rem;
    if      (i < 24576) { W = W1; ncols = 384; ooff = WF_W1; rem = i; }
    else if (i < 49152) { W = W2; ncols = 384; ooff = WF_W2; rem = i - 24576; }
    else if (i < 57344) { W = L1; ncols = 128; ooff = WF_L1; rem = i - 49152; }
    else if (i < 65536) { W = L2; ncols = 128; ooff = WF_L2; rem = i - 57344; }
    else if (i < 73728) { W = L3; ncols = 128; ooff = WF_L3; rem = i - 65536; }
    else                { W = L4; ncols = 128; ooff = WF_L4; rem = i - 73728; }
    int g = rem >> 6, idx = rem & 63;
    int lane = idx >> 1, reg = idx & 1;
    int nt = g & 7, wn = (g >> 3) & 1, ch = (g >> 4) & 7, cb = g >> 7;
    int k = ch*16 + reg*8 + (lane & 3)*2;
    int n = cb*128 + wn*64 + nt*8 + (lane >> 2);
    float e0 = W[k*ncols + n];
    float e1 = W[(k+1)*ncols + n];
    uint32_t loW;
    uint32_t hiW = bfpack2(e0, e1, loW);
    g_wf[ooff + g*128 + lane*4 + reg]     = hiW;
    g_wf[ooff + g*128 + lane*4 + 2 + reg] = loW;
}

__global__ void presplit_a_kernel(const float* __restrict__ X)
{
    int i = blockIdx.x*blockDim.x + threadIdx.x;
    if (i >= MBLKS*128*64) return;
    int row = i >> 6, k = (i & 63)*2;
    float e0 = 0.f, e1 = 0.f;
    if (row < NN) {
        e0 = X[row*128 + k];
        e1 = X[row*128 + k + 1];
    }
    uint32_t loW;
    uint32_t hiW = bfpack2(e0, e1, loW);
    int a = frag_addr(row, k);
    g_afrag[a]       = hiW;
    g_afrag[a + 128] = loW;
}

// ---------------- CSR build ----------------------------------------------
__global__ void zero_deg_kernel() {
    int i = blockIdx.x*blockDim.x + threadIdx.x;
    if (i < NN) g_deg[i] = 0;
}

__global__ void hist_kernel(const int* __restrict__ dst) {
    int i = blockIdx.x*blockDim.x + threadIdx.x;
    if (i < EE) atomicAdd(&g_deg[dst[i]], 1);
}

__global__ void scan_kernel() {
    __shared__ int sh[1024];
    int t = threadIdx.x;
    const int ITEMS = (NN + 1023) / 1024;
    int base = t * ITEMS;
    int s = 0;
    for (int i = 0; i < ITEMS; i++) {
        int idx = base + i;
        if (idx < NN) s += g_deg[idx];
    }
    sh[t] = s;
    __syncthreads();
    for (int off = 1; off < 1024; off <<= 1) {
        int v = (t >= off) ? sh[t - off] : 0;
        __syncthreads();
        sh[t] += v;
        __syncthreads();
    }
    int run = sh[t] - s;
    for (int i = 0; i < ITEMS; i++) {
        int idx = base + i;
        if (idx < NN) {
            g_rowptr[idx] = run;
            g_wptr[idx]   = run;
            run += g_deg[idx];
        }
    }
    if (t == 0) g_rowptr[NN] = EE;
}

__global__ void scatter_kernel(const int* __restrict__ src, const int* __restrict__ dst) {
    int i = blockIdx.x*blockDim.x + threadIdx.x;
    if (i < EE) {
        int d = dst[i];
        int p = atomicAdd(&g_wptr[d], 1);
        g_srcs[p] = src[i];
    }
}

// ------------- bf16x3 tensor-core GEMM, pre-split fragment smem ----------
// AMODE 0: A from g_afrag (pure copy). AMODE 1: A float rows, in-kernel split.
// B always from g_wf[wfoff]. C(MxNcols)=A@B [+bias][+leaky 0.01].
// al != nullptr: attention dots for head hh=blockIdx.x -> g_el/g_er.
template<int AMODE>
__global__ __launch_bounds__(256, 2)
void bf16gemm_kernel(const float* __restrict__ A, int wfoff,
                     const float* __restrict__ bias, float* __restrict__ C,
                     int M, int Ncols, int act,
                     const float* __restrict__ al, const float* __restrict__ ar)
{
    __shared__ __align__(16) uint32_t As[2048];  // mtile*256 + plane*128 + lane*4 + reg
    __shared__ __align__(16) uint32_t Bs[2048];  // (wn*8+nt)*128 + lane*4 + plane*2 + reg
    __shared__ float sEl[2][128], sEr[2][128];

    int tid  = threadIdx.x;
    int lane = tid & 31, warp = tid >> 5;
    int wm = warp >> 1, wn = warp & 1;
    int mblk = blockIdx.y, cb = blockIdx.x;
    int m0 = mblk*128, col0 = cb*128;

    float acc[2][8][4];
    #pragma unroll
    for (int i = 0; i < 2; i++)
        #pragma unroll
        for (int j = 0; j < 8; j++)
            #pragma unroll
            for (int q = 0; q < 4; q++) acc[i][j][q] = 0.f;

    const uint32_t* wf = &g_wf[wfoff + cb*16384];
    const uint32_t* af = &g_afrag[mblk*16384];

    uint4 bpr[2], apr[2];
    float4 a0f, a1f;
    const float4 z4 = make_float4(0.f,0.f,0.f,0.f);

    // prefetch chunk 0
    bpr[0] = *(const uint4*)&wf[tid*8];
    bpr[1] = *(const uint4*)&wf[tid*8 + 4];
    if (AMODE == 0) {
        apr[0] = *(const uint4*)&af[tid*8];
        apr[1] = *(const uint4*)&af[tid*8 + 4];
    } else {
        int gr = m0 + (tid >> 1);
        const float* ap = &A[(size_t)gr*128 + (tid & 1)*8];
        a0f = (gr < M) ? *(const float4*)ap       : z4;
        a1f = (gr < M) ? *(const float4*)(ap + 4) : z4;
    }

    #pragma unroll 1
    for (int ch = 0; ch < 8; ch++) {
        if (ch) __syncthreads();
        // ---- store B (pure copy) ----
        *(uint4*)&Bs[tid*8]     = bpr[0];
        *(uint4*)&Bs[tid*8 + 4] = bpr[1];
        // ---- store A ----
        if (AMODE == 0) {
            *(uint4*)&As[tid*8]     = apr[0];
            *(uint4*)&As[tid*8 + 4] = apr[1];
        } else {
            int row = tid >> 1, kh = tid & 1;
            int mtile = row >> 4, r16 = row & 15;
            int regb = kh*2 + (r16 >> 3);
            uint32_t* bp = &As[mtile*256];
            float v[8] = {a0f.x,a0f.y,a0f.z,a0f.w, a1f.x,a1f.y,a1f.z,a1f.w};
            #pragma unroll
            for (int p = 0; p < 4; p++) {
                uint32_t loW;
                uint32_t hiW = bfpack2(v[2*p], v[2*p+1], loW);
                int ln = (r16 & 7)*4 + p;
                bp[ln*4 + regb]       = hiW;
                bp[128 + ln*4 + regb] = loW;
            }
        }
        __syncthreads();
        if (ch < 7) {   // prefetch next chunk (overlaps mma)
            bpr[0] = *(const uint4*)&wf[(ch+1)*2048 + tid*8];
            bpr[1] = *(const uint4*)&wf[(ch+1)*2048 + tid*8 + 4];
            if (AMODE == 0) {
                apr[0] = *(const uint4*)&af[(ch+1)*2048 + tid*8];
                apr[1] = *(const uint4*)&af[(ch+1)*2048 + tid*8 + 4];
            } else {
                int gr = m0 + (tid >> 1);
                const float* ap = &A[(size_t)gr*128 + (ch+1)*16 + (tid & 1)*8];
                a0f = (gr < M) ? *(const float4*)ap       : z4;
                a1f = (gr < M) ? *(const float4*)(ap + 4) : z4;
            }
        }
        // ---- mma: 48 HMMA.16816 per warp per chunk ----
        uint4 ah[2], alo2[2];
        #pragma unroll
        for (int mt = 0; mt < 2; mt++) {
            int base = (wm*2 + mt)*256;
            ah[mt]   = *(const uint4*)&As[base + lane*4];
            alo2[mt] = *(const uint4*)&As[base + 128 + lane*4];
        }
        #pragma unroll
        for (int ng = 0; ng < 4; ng++) {
            int nA = 2*ng, nB = 2*ng + 1;
            uint4 b0 = *(const uint4*)&Bs[(wn*8 + nA)*128 + lane*4];  // {h0,h1,l0,l1}
            uint4 b1 = *(const uint4*)&Bs[(wn*8 + nB)*128 + lane*4];
            // term 1: Ahi * Bhi
            mma16(acc[0][nA], (const uint32_t*)&ah[0],   b0.x, b0.y);
            mma16(acc[1][nA], (const uint32_t*)&ah[1],   b0.x, b0.y);
            mma16(acc[0][nB], (const uint32_t*)&ah[0],   b1.x, b1.y);
            mma16(acc[1][nB], (const uint32_t*)&ah[1],   b1.x, b1.y);
            // term 2: Ahi * Blo
            mma16(acc[0][nA], (const uint32_t*)&ah[0],   b0.z, b0.w);
            mma16(acc[1][nA], (const uint32_t*)&ah[1],   b0.z, b0.w);
            mma16(acc[0][nB], (const uint32_t*)&ah[0],   b1.z, b1.w);
            mma16(acc[1][nB], (const uint32_t*)&ah[1],   b1.z, b1.w);
            // term 3: Alo * Bhi
            mma16(acc[0][nA], (const uint32_t*)&alo2[0], b0.x, b0.y);
            mma16(acc[1][nA], (const uint32_t*)&alo2[1], b0.x, b0.y);
            mma16(acc[0][nB], (const uint32_t*)&alo2[0], b1.x, b1.y);
            mma16(acc[1][nB], (const uint32_t*)&alo2[1], b1.x, b1.y);
        }
    }

    // ---------------- epilogue: store C (C frag layout same as k8) -------
    #pragma unroll
    for (int mt = 0; mt < 2; mt++) {
        #pragma unroll
        for (int half = 0; half < 2; half++) {
            int r = m0 + wm*32 + mt*16 + (lane >> 2) + half*8;
            if (r >= M) continue;
            #pragma unroll
            for (int nt = 0; nt < 8; nt++) {
                int c = col0 + wn*64 + nt*8 + 2*(lane & 3);
                float v0 = acc[mt][nt][half*2 + 0];
                float v1 = acc[mt][nt][half*2 + 1];
                if (bias) { v0 += bias[c]; v1 += bias[c+1]; }
                if (act)  { v0 = v0 > 0.f ? v0 : 0.01f*v0;
                            v1 = v1 > 0.f ? v1 : 0.01f*v1; }
                *(float2*)&C[(size_t)r*Ncols + c] = make_float2(v0, v1);
            }
        }
    }

    // ---------------- fused attention dots (GAT path) --------------------
    if (al) {
        int hh = blockIdx.x;
        float alv[8][2], arv[8][2];
        #pragma unroll
        for (int nt = 0; nt < 8; nt++)
            #pragma unroll
            for (int j = 0; j < 2; j++) {
                int c = wn*64 + nt*8 + 2*(lane & 3) + j;
                alv[nt][j] = __ldg(&al[hh*HIDN + c]);
                arv[nt][j] = __ldg(&ar[hh*HIDN + c]);
            }
        #pragma unroll
        for (int mt = 0; mt < 2; mt++) {
            #pragma unroll
            for (int half = 0; half < 2; half++) {
                float pl = 0.f, pr = 0.f;
                #pragma unroll
                for (int nt = 0; nt < 8; nt++)
                    #pragma unroll
                    for (int j = 0; j < 2; j++) {
                        float v = acc[mt][nt][half*2 + j];
                        pl += v * alv[nt][j];
                        pr += v * arv[nt][j];
                    }
                pl += __shfl_xor_sync(0xffffffffu, pl, 1);
                pl += __shfl_xor_sync(0xffffffffu, pl, 2);
                pr += __shfl_xor_sync(0xffffffffu, pr, 1);
                pr += __shfl_xor_sync(0xffffffffu, pr, 2);
                if ((lane & 3) == 0) {
                    int rl = wm*32 + mt*16 + (lane >> 2) + half*8;
                    sEl[wn][rl] = pl;
                    sEr[wn][rl] = pr;
                }
            }
        }
        __syncthreads();
        if (tid < 128) {
            int r = m0 + tid;
            if (r < M) {
                g_el[r*HH + hh] = sEl[0][tid] + sEl[1][tid];
                g_er[r*HH + hh] = sEr[0][tid] + sEr[1][tid];
            }
        }
    }
}

// ---- fused softmax + aggregation, block (96 thr) per node ---------------
__global__ __launch_bounds__(96)
void agg_kernel(const float* __restrict__ bias, int writeFrag)
{
    __shared__ int    sSrc[CAP];
    __shared__ float  sE[3][CAP];
    __shared__ float4 sh4[3][32];
    int n = blockIdx.x;
    int t = threadIdx.x, head = t >> 5, lane = t & 31;
    int beg = g_rowptr[n], end = g_rowptr[n+1];
    int deg = end - beg;
    int cached = deg < CAP ? deg : CAP;
    for (int j = t; j < cached; j += 96) sSrc[j] = g_srcs[beg + j];
    __syncthreads();

    float er_n = g_er[n*HH + head];
    float mx = -1e30f;
    for (int j = lane; j < deg; j += 32) {
        int s = (j < CAP) ? sSrc[j] : g_srcs[beg + j];
        float v = g_el[s*HH + head] + er_n;
        v = v > 0.f ? v : 0.2f*v;
        if (j < CAP) sE[head][j] = v;
        mx = fmaxf(mx, v);
    }
    #pragma unroll
    for (int o = 16; o; o >>= 1) mx = fmaxf(mx, __shfl_xor_sync(0xffffffffu, mx, o));
    float sum = 0.f;
    for (int j = lane; j < deg; j += 32) {
        float v;
        if (j < CAP) v = sE[head][j];
        else {
            int s = g_srcs[beg + j];
            v = g_el[s*HH + head] + er_n;
            v = v > 0.f ? v : 0.2f*v;
        }
        float e = expf(v - mx);
        if (j < CAP) sE[head][j] = e;
        sum += e;
    }
    #pragma unroll
    for (int o = 16; o; o >>= 1) sum += __shfl_xor_sync(0xffffffffu, sum, o);
    float inv = 1.f / (sum + 1e-9f);
    __syncwarp();

    const float* hb = &g_h[(size_t)head*HIDN + lane*4];
    float4 a = make_float4(0.f, 0.f, 0.f, 0.f);
    int jn = 0;
    for (; jn + 1 < cached; jn += 2) {
        int   s0 = sSrc[jn],      s1 = sSrc[jn+1];
        float w0 = sE[head][jn],  w1 = sE[head][jn+1];
        float4 v0 = *(const float4*)&hb[(size_t)s0*HF];
        float4 v1 = *(const float4*)&hb[(size_t)s1*HF];
        a.x += w0*v0.x + w1*v1.x;
        a.y += w0*v0.y + w1*v1.y;
        a.z += w0*v0.z + w1*v1.z;
        a.w += w0*v0.w + w1*v1.w;
    }
    for (; jn < cached; jn++) {
        int s = sSrc[jn];
        float w = sE[head][jn];
        float4 v = *(const float4*)&hb[(size_t)s*HF];
        a.x += w*v.x; a.y += w*v.y; a.z += w*v.z; a.w += w*v.w;
    }
    for (int j = beg + CAP; j < end; j++) {      // rare fallback
        int s = g_srcs[j];
        float v = g_el[s*HH + head] + er_n;
        v = v > 0.f ? v : 0.2f*v;
        float w = expf(v - mx);
        float4 v4 = *(const float4*)&hb[(size_t)s*HF];
        a.x += w*v4.x; a.y += w*v4.y; a.z += w*v4.z; a.w += w*v4.w;
    }

    const float4 b4 = *(const float4*)&bias[head*HIDN + lane*4];
    a.x = a.x*inv + b4.x;  a.y = a.y*inv + b4.y;
    a.z = a.z*inv + b4.z;  a.w = a.w*inv + b4.w;
    a.x = a.x > 0.f ? a.x : 0.01f*a.x;
    a.y = a.y > 0.f ? a.y : 0.01f*a.y;
    a.z = a.z > 0.f ? a.z : 0.01f*a.z;
    a.w = a.w > 0.f ? a.w : 0.01f*a.w;
    sh4[head][lane] = a;
    __syncthreads();
    if (t < 32) {
        float4 r0 = sh4[0][t], r1 = sh4[1][t], r2 = sh4[2][t];
        float o[4];
        o[0] = (r0.x + r1.x + r2.x) * (1.f/3.f);
        o[1] = (r0.y + r1.y + r2.y) * (1.f/3.f);
        o[2] = (r0.z + r1.z + r2.z) * (1.f/3.f);
        o[3] = (r0.w + r1.w + r2.w) * (1.f/3.f);
        *(float4*)&g_x[(size_t)n*HIDN + t*4] = make_float4(o[0],o[1],o[2],o[3]);
        if (writeFrag) {
            uint32_t lo01, lo23;
            uint32_t hi01 = bfpack2(o[0], o[1], lo01);
            uint32_t hi23 = bfpack2(o[2], o[3], lo23);
            int a0 = frag_addr(n, t*4);
            int a2 = frag_addr(n, t*4 + 2);
            g_afrag[a0]       = hi01;
            g_afrag[a0 + 128] = lo01;
            g_afrag[a2]       = hi23;
            g_afrag[a2 + 128] = lo23;
        }
    }
}

// ---------------- classifier: (N,128)@(128,6)+b, warp per node -----------
__global__ void classifier_kernel(const float* __restrict__ lw5, const float* __restrict__ lb5,
                                  float* __restrict__ out)
{
    int gw   = (blockIdx.x*blockDim.x + threadIdx.x) >> 5;
    int lane = threadIdx.x & 31;
    if (gw >= NN) return;
    const float* xr = &g_x[(size_t)gw*HIDN];
    float acc[NCLS] = {};
    #pragma unroll
    for (int k = lane; k < HIDN; k += 32) {
        float xv = xr[k];
        #pragma unroll
        for (int c = 0; c < NCLS; c++) acc[c] += xv * __ldg(&lw5[k*NCLS + c]);
    }
    #pragma unroll
    for (int c = 0; c < NCLS; c++)
        #pragma unroll
        for (int o = 16; o; o >>= 1) acc[c] += __shfl_xor_sync(0xffffffffu, acc[c], o);
    if (lane == 0) {
        #pragma unroll
        for (int c = 0; c < NCLS; c++) out[gw*NCLS + c] = acc[c] + lb5[c];
    }
}

// -------------------------------------------------------------------------
extern "C" void kernel_launch(void* const* d_in, const int* in_sizes, int n_in,
                              void* d_out, int out_size)
{
    const float* in_feat = (const float*)d_in[0];
    const int*   src     = (const int*)  d_in[1];
    const int*   dst     = (const int*)  d_in[2];
    const float* W1  = (const float*)d_in[3];
    const float* al1 = (const float*)d_in[4];
    const float* ar1 = (const float*)d_in[5];
    const float* b1  = (const float*)d_in[6];
    const float* W2  = (const float*)d_in[7];
    const float* al2 = (const float*)d_in[8];
    const float* ar2 = (const float*)d_in[9];
    const float* b2  = (const float*)d_in[10];
    const float* lw1 = (const float*)d_in[11];
    const float* lb1 = (const float*)d_in[12];
    const float* lw2 = (const float*)d_in[13];
    const float* lb2 = (const float*)d_in[14];
    const float* lw3 = (const float*)d_in[15];
    const float* lb3 = (const float*)d_in[16];
    const float* lw4 = (const float*)d_in[17];
    const float* lb4 = (const float*)d_in[18];
    const float* lw5 = (const float*)d_in[19];
    const float* lb5 = (const float*)d_in[20];
    float* out = (float*)d_out;

    float *ph, *px, *py;
    cudaGetSymbolAddress((void**)&ph, g_h);
    cudaGetSymbolAddress((void**)&px, g_x);
    cudaGetSymbolAddress((void**)&py, g_y);

    const int TB = 256;

    dim3 g_gat(HF/128, MBLKS);     // (3, 391)
    dim3 g_mlp(1, MBLKS);

    // pre-splits first (gemm1 stays the 4th launch for ncu)
    presplit_w_kernel<<<(81920 + TB - 1)/TB, TB>>>(W1, W2, lw1, lw2, lw3, lw4);
    presplit_a_kernel<<<(MBLKS*128*64 + TB - 1)/TB, TB>>>(in_feat);
    zero_deg_kernel<<<(NN + TB - 1)/TB, TB>>>();

    // ---- GAT layer 1 GEMM (independent of CSR build) ----
    bf16gemm_kernel<0><<<g_gat, 256>>>(nullptr, WF_W1, nullptr, ph, NN, HF, 0, al1, ar1);

    // CSR build
    hist_kernel<<<(EE + TB - 1)/TB, TB>>>(dst);
    scan_kernel<<<1, 1024>>>();
    scatter_kernel<<<(EE + TB - 1)/TB, TB>>>(src, dst);

    // ---- GAT layer 1 edge phase (fused softmax + aggregate) ----
    agg_kernel<<<NN, 96>>>(b1, 1);   // writes g_x + g_afrag

    // ---- GAT layer 2 ----
    bf16gemm_kernel<0><<<g_gat, 256>>>(nullptr, WF_W2, nullptr, ph, NN, HF, 0, al2, ar2);
    agg_kernel<<<NN, 96>>>(b2, 0);

    // ---- MLP head ----
    bf16gemm_kernel<1><<<g_mlp, 256>>>(px, WF_L1, lb1, py, NN, HIDN, 1, nullptr, nullptr);
    bf16gemm_kernel<1><<<g_mlp, 256>>>(py, WF_L2, lb2, px, NN, HIDN, 1, nullptr, nullptr);
    bf16gemm_kernel<1><<<g_mlp, 256>>>(px, WF_L3, lb3, py, NN, HIDN, 1, nullptr, nullptr);
    bf16gemm_kernel<1><<<g_mlp, 256>>>(py, WF_L4, lb4, px, NN, HIDN, 1, nullptr, nullptr);
    classifier_kernel<<<(NN + 7)/8, 256>>>(lw5, lb5, out);
}

// round 9
// speedup vs baseline: 1.4710x; 1.0927x over previous
#include <cuda_runtime.h>
#include <cuda_bf16.h>
#include <cuda_fp16.h>
#include <cstdint>

#define NN 50000
#define EE 800000
#define HH 3
#define HIDN 128
#define HF (HH*HIDN)   // 384
#define NCLS 6
#define MBLKS 391      // ceil(50000/128)
#define CAP 128        // per-node cached-edge capacity in fused agg kernel
#define FRAGW (MBLKS*16384)

// weight-fragment scratch offsets (words); bf16 hi/lo packed 2-per-word
#define WF_W1  0
#define WF_W2  49152
#define WF_L1  98304
#define WF_L2  114688
#define WF_L3  131072
#define WF_L4  147456
#define WF_TOT 163840

// ---------------- scratch (device globals; no allocation allowed) --------
__device__ __half   g_h[NN*HF];     // post-GEMM per-head features (fp16)
__device__ float    g_x[NN*HIDN];   // classifier input
__device__ float    g_el[NN*HH];
__device__ float    g_er[NN*HH];
__device__ int      g_srcs[EE];     // src node id in CSR order
__device__ int      g_deg[NN];
__device__ int      g_rowptr[NN+1];
__device__ int      g_wptr[NN];
__device__ uint32_t g_wf[WF_TOT];   // pre-split bf16 weight frags
__device__ uint32_t g_afragA[FRAGW];
__device__ uint32_t g_afragB[FRAGW];

// ---------------- helpers -------------------------------------------------
__device__ __forceinline__ uint32_t bfpack2(float e0, float e1, uint32_t& loW) {
    __nv_bfloat16 h0 = __float2bfloat16_rn(e0);
    __nv_bfloat16 h1 = __float2bfloat16_rn(e1);
    float r0 = e0 - __bfloat162float(h0);
    float r1 = e1 - __bfloat162float(h1);
    __nv_bfloat16 l0 = __float2bfloat16_rn(r0);
    __nv_bfloat16 l1 = __float2bfloat16_rn(r1);
    loW = (uint32_t)__bfloat16_as_ushort(l0) | ((uint32_t)__bfloat16_as_ushort(l1) << 16);
    return (uint32_t)__bfloat16_as_ushort(h0) | ((uint32_t)__bfloat16_as_ushort(h1) << 16);
}
__device__ __forceinline__ void mma16(float* c, const uint32_t* a, uint32_t b0, uint32_t b1) {
    asm("mma.sync.aligned.m16n8k16.row.col.f32.bf16.bf16.f32 "
        "{%0,%1,%2,%3}, {%4,%5,%6,%7}, {%8,%9}, {%0,%1,%2,%3};"
        : "+f"(c[0]), "+f"(c[1]), "+f"(c[2]), "+f"(c[3])
        : "r"(a[0]), "r"(a[1]), "r"(a[2]), "r"(a[3]), "r"(b0), "r"(b1));
}
// A-fragment word address (hi plane; lo at +128) for element (row, k even)
__device__ __forceinline__ int frag_addr(int row, int k) {
    int mblk = row >> 7, ch = k >> 4, mtile = (row >> 4) & 7;
    int r16 = row & 15, k16 = k & 15;
    int reg  = (k16 >> 3)*2 + (r16 >> 3);
    int lane = (r16 & 7)*4 + ((k16 >> 1) & 3);
    return ((mblk*8 + ch)*8 + mtile)*256 + lane*4 + reg;
}
__device__ __forceinline__ uint4 ldg4(const uint32_t* p) {
    return *reinterpret_cast<const uint4*>(p);
}

// ---------------- pre-split kernels --------------------------------------
__global__ void presplit_w_kernel(const float* __restrict__ W1, const float* __restrict__ W2,
                                  const float* __restrict__ L1, const float* __restrict__ L2,
                                  const float* __restrict__ L3, const float* __restrict__ L4)
{
    int i = blockIdx.x*blockDim.x + threadIdx.x;
    if (i >= 81920) return;
    const float* W; int ncols, ooff, rem;
    if      (i < 24576) { W = W1; ncols = 384; ooff = WF_W1; rem = i; }
    else if (i < 49152) { W = W2; ncols = 384; ooff = WF_W2; rem = i - 24576; }
    else if (i < 57344) { W = L1; ncols = 128; ooff = WF_L1; rem = i - 49152; }
    else if (i < 65536) { W = L2; ncols = 128; ooff = WF_L2; rem = i - 57344; }
    else if (i < 73728) { W = L3; ncols = 128; ooff = WF_L3; rem = i - 65536; }
    else                { W = L4; ncols = 128; ooff = WF_L4; rem = i - 73728; }
    int g = rem >> 6, idx = rem & 63;
    int lane = idx >> 1, reg = idx & 1;
    int nt = g & 7, wn = (g >> 3) & 1, ch = (g >> 4) & 7, cb = g >> 7;
    int k = ch*16 + reg*8 + (lane & 3)*2;
    int n = cb*128 + wn*64 + nt*8 + (lane >> 2);
    float e0 = W[k*ncols + n];
    float e1 = W[(k+1)*ncols + n];
    uint32_t loW;
    uint32_t hiW = bfpack2(e0, e1, loW);
    g_wf[ooff + g*128 + lane*4 + reg]     = hiW;
    g_wf[ooff + g*128 + lane*4 + 2 + reg] = loW;
}

__global__ void presplit_a_kernel(const float* __restrict__ X)
{
    int i = blockIdx.x*blockDim.x + threadIdx.x;
    if (i >= MBLKS*128*64) return;
    int row = i >> 6, k = (i & 63)*2;
    float e0 = 0.f, e1 = 0.f;
    if (row < NN) {
        e0 = X[row*128 + k];
        e1 = X[row*128 + k + 1];
    }
    uint32_t loW;
    uint32_t hiW = bfpack2(e0, e1, loW);
    int a = frag_addr(row, k);
    g_afragA[a]       = hiW;
    g_afragA[a + 128] = loW;
}

// ---------------- CSR build ----------------------------------------------
__global__ void zero_deg_kernel() {
    int i = blockIdx.x*blockDim.x + threadIdx.x;
    if (i < NN) g_deg[i] = 0;
}

__global__ void hist_kernel(const int* __restrict__ dst) {
    int i = blockIdx.x*blockDim.x + threadIdx.x;
    if (i < EE) atomicAdd(&g_deg[dst[i]], 1);
}

__global__ void scan_kernel() {
    __shared__ int sh[1024];
    int t = threadIdx.x;
    const int ITEMS = (NN + 1023) / 1024;
    int base = t * ITEMS;
    int s = 0;
    for (int i = 0; i < ITEMS; i++) {
        int idx = base + i;
        if (idx < NN) s += g_deg[idx];
    }
    sh[t] = s;
    __syncthreads();
    for (int off = 1; off < 1024; off <<= 1) {
        int v = (t >= off) ? sh[t - off] : 0;
        __syncthreads();
        sh[t] += v;
        __syncthreads();
    }
    int run = sh[t] - s;
    for (int i = 0; i < ITEMS; i++) {
        int idx = base + i;
        if (idx < NN) {
            g_rowptr[idx] = run;
            g_wptr[idx]   = run;
            run += g_deg[idx];
        }
    }
    if (t == 0) g_rowptr[NN] = EE;
}

__global__ void scatter_kernel(const int* __restrict__ src, const int* __restrict__ dst) {
    int i = blockIdx.x*blockDim.x + threadIdx.x;
    if (i < EE) {
        int d = dst[i];
        int p = atomicAdd(&g_wptr[d], 1);
        g_srcs[p] = src[i];
    }
}

// ------------- bf16x3 tensor-core GEMM, smem-free (register frags) -------
// A frags from af (fragment order), B frags from wfp. No shared memory in
// the mainloop; every warp LDGs its own fragments (B is L1-resident).
// OUT 0: C -> g_h fp16 + attention dots to g_el/g_er (GAT; no bias/act)
// OUT 1: C -> fragOut in A-fragment order with bias+leaky (MLP mid)
// OUT 2: C -> Cf32 (stride 128) with bias+leaky (MLP last)
template<int OUT>
__global__ __launch_bounds__(256, 2)
void gemm_kernel(const uint32_t* __restrict__ af, const uint32_t* __restrict__ wfp,
                 const float* __restrict__ bias, float* __restrict__ Cf32,
                 uint32_t* __restrict__ fragOut, int M,
                 const float* __restrict__ al, const float* __restrict__ ar)
{
    __shared__ float sEl[2][128], sEr[2][128];
    int tid  = threadIdx.x;
    int lane = tid & 31, warp = tid >> 5;
    int wm = warp >> 1, wn = warp & 1;
    int mblk = blockIdx.y, cb = blockIdx.x;
    int m0 = mblk*128, col0 = cb*128;

    float acc[2][8][4];
    #pragma unroll
    for (int i = 0; i < 2; i++)
        #pragma unroll
        for (int j = 0; j < 8; j++)
            #pragma unroll
            for (int q = 0; q < 4; q++) acc[i][j][q] = 0.f;

    const uint32_t* afb = af  + mblk*16384;
    const uint32_t* wfb = wfp + cb*16384;

    #pragma unroll 2
    for (int ch = 0; ch < 8; ch++) {
        uint4 ah[2], alo[2];
        #pragma unroll
        for (int mt = 0; mt < 2; mt++) {
            int base = (ch*8 + wm*2 + mt)*256 + lane*4;
            ah[mt]  = ldg4(&afb[base]);
            alo[mt] = ldg4(&afb[base + 128]);
        }
        #pragma unroll
        for (int ng = 0; ng < 4; ng++) {
            int nA = 2*ng, nB = 2*ng + 1;
            uint4 b0 = ldg4(&wfb[(ch*16 + wn*8 + nA)*128 + lane*4]);  // {h0,h1,l0,l1}
            uint4 b1 = ldg4(&wfb[(ch*16 + wn*8 + nB)*128 + lane*4]);
            // term 1: Ahi*Bhi
            mma16(acc[0][nA], (const uint32_t*)&ah[0],  b0.x, b0.y);
            mma16(acc[1][nA], (const uint32_t*)&ah[1],  b0.x, b0.y);
            mma16(acc[0][nB], (const uint32_t*)&ah[0],  b1.x, b1.y);
            mma16(acc[1][nB], (const uint32_t*)&ah[1],  b1.x, b1.y);
            // term 2: Ahi*Blo
            mma16(acc[0][nA], (const uint32_t*)&ah[0],  b0.z, b0.w);
            mma16(acc[1][nA], (const uint32_t*)&ah[1],  b0.z, b0.w);
            mma16(acc[0][nB], (const uint32_t*)&ah[0],  b1.z, b1.w);
            mma16(acc[1][nB], (const uint32_t*)&ah[1],  b1.z, b1.w);
            // term 3: Alo*Bhi
            mma16(acc[0][nA], (const uint32_t*)&alo[0], b0.x, b0.y);
            mma16(acc[1][nA], (const uint32_t*)&alo[1], b0.x, b0.y);
            mma16(acc[0][nB], (const uint32_t*)&alo[0], b1.x, b1.y);
            mma16(acc[1][nB], (const uint32_t*)&alo[1], b1.x, b1.y);
        }
    }

    if (OUT == 0) {
        // ---- fp16 h store ----
        #pragma unroll
        for (int mt = 0; mt < 2; mt++) {
            #pragma unroll
            for (int half = 0; half < 2; half++) {
                int r = m0 + wm*32 + mt*16 + (lane >> 2) + half*8;
                if (r >= M) continue;
                #pragma unroll
                for (int nt = 0; nt < 8; nt++) {
                    int c = col0 + wn*64 + nt*8 + 2*(lane & 3);
                    __half2 hv = __float22half2_rn(
                        make_float2(acc[mt][nt][half*2 + 0], acc[mt][nt][half*2 + 1]));
                    *reinterpret_cast<__half2*>(&g_h[(size_t)r*HF + c]) = hv;
                }
            }
        }
        // ---- fused attention dots ----
        int hh = blockIdx.x;
        float alv[8][2], arv[8][2];
        #pragma unroll
        for (int nt = 0; nt < 8; nt++)
            #pragma unroll
            for (int j = 0; j < 2; j++) {
                int c = wn*64 + nt*8 + 2*(lane & 3) + j;
                alv[nt][j] = __ldg(&al[hh*HIDN + c]);
                arv[nt][j] = __ldg(&ar[hh*HIDN + c]);
            }
        #pragma unroll
        for (int mt = 0; mt < 2; mt++) {
            #pragma unroll
            for (int half = 0; half < 2; half++) {
                float pl = 0.f, pr = 0.f;
                #pragma unroll
                for (int nt = 0; nt < 8; nt++)
                    #pragma unroll
                    for (int j = 0; j < 2; j++) {
                        float v = acc[mt][nt][half*2 + j];
                        pl += v * alv[nt][j];
                        pr += v * arv[nt][j];
                    }
                pl += __shfl_xor_sync(0xffffffffu, pl, 1);
                pl += __shfl_xor_sync(0xffffffffu, pl, 2);
                pr += __shfl_xor_sync(0xffffffffu, pr, 1);
                pr += __shfl_xor_sync(0xffffffffu, pr, 2);
                if ((lane & 3) == 0) {
                    int rl = wm*32 + mt*16 + (lane >> 2) + half*8;
                    sEl[wn][rl] = pl;
                    sEr[wn][rl] = pr;
                }
            }
        }
        __syncthreads();
        if (tid < 128) {
            int r = m0 + tid;
            if (r < M) {
                g_el[r*HH + hh] = sEl[0][tid] + sEl[1][tid];
                g_er[r*HH + hh] = sEr[0][tid] + sEr[1][tid];
            }
        }
    } else if (OUT == 1) {
        // ---- bias + leaky + direct A-fragment store for next GEMM ----
        #pragma unroll
        for (int mt = 0; mt < 2; mt++) {
            #pragma unroll
            for (int ng = 0; ng < 4; ng++) {
                int ntE = 2*ng, ntO = 2*ng + 1;
                int cE = wn*64 + ntE*8 + 2*(lane & 3);
                float bE0 = bias[cE],     bE1 = bias[cE + 1];
                float bO0 = bias[cE + 8], bO1 = bias[cE + 9];
                float e0 = acc[mt][ntE][0] + bE0, e1 = acc[mt][ntE][1] + bE1;
                float e2 = acc[mt][ntE][2] + bE0, e3 = acc[mt][ntE][3] + bE1;
                float o0 = acc[mt][ntO][0] + bO0, o1 = acc[mt][ntO][1] + bO1;
                float o2 = acc[mt][ntO][2] + bO0, o3 = acc[mt][ntO][3] + bO1;
                e0 = e0 > 0.f ? e0 : 0.01f*e0;  e1 = e1 > 0.f ? e1 : 0.01f*e1;
                e2 = e2 > 0.f ? e2 : 0.01f*e2;  e3 = e3 > 0.f ? e3 : 0.01f*e3;
                o0 = o0 > 0.f ? o0 : 0.01f*o0;  o1 = o1 > 0.f ? o1 : 0.01f*o1;
                o2 = o2 > 0.f ? o2 : 0.01f*o2;  o3 = o3 > 0.f ? o3 : 0.01f*o3;
                uint32_t l0, l1, l2, l3;
                uint32_t h0 = bfpack2(e0, e1, l0);   // reg0: (half0, ntE)
                uint32_t h1 = bfpack2(e2, e3, l1);   // reg1: (half1, ntE)
                uint32_t h2 = bfpack2(o0, o1, l2);   // reg2: (half0, ntO)
                uint32_t h3 = bfpack2(o2, o3, l3);   // reg3: (half1, ntO)
                int base = ((mblk*8 + wn*4 + ng)*8 + wm*2 + mt)*256 + lane*4;
                *reinterpret_cast<uint4*>(&fragOut[base])       = make_uint4(h0, h1, h2, h3);
                *reinterpret_cast<uint4*>(&fragOut[base + 128]) = make_uint4(l0, l1, l2, l3);
            }
        }
    } else {
        // ---- fp32 store with bias + leaky (classifier input) ----
        #pragma unroll
        for (int mt = 0; mt < 2; mt++) {
            #pragma unroll
            for (int half = 0; half < 2; half++) {
                int r = m0 + wm*32 + mt*16 + (lane >> 2) + half*8;
                if (r >= M) continue;
                #pragma unroll
                for (int nt = 0; nt < 8; nt++) {
                    int c = wn*64 + nt*8 + 2*(lane & 3);
                    float v0 = acc[mt][nt][half*2 + 0] + bias[c];
                    float v1 = acc[mt][nt][half*2 + 1] + bias[c + 1];
                    v0 = v0 > 0.f ? v0 : 0.01f*v0;
                    v1 = v1 > 0.f ? v1 : 0.01f*v1;
                    *(float2*)&Cf32[(size_t)r*HIDN + c] = make_float2(v0, v1);
                }
            }
        }
    }
}

// ---- fused softmax + aggregation, block (96 thr) per node ---------------
// Warp = head. fp16 h gather. Epilogue: inv-denom, bias, leaky(0.01),
// head-mean -> g_x + next-layer A fragments.
__global__ __launch_bounds__(96)
void agg_kernel(const float* __restrict__ bias, uint32_t* __restrict__ fragOut)
{
    __shared__ int    sSrc[CAP];
    __shared__ float  sE[3][CAP];
    __shared__ float4 sh4[3][32];
    int n = blockIdx.x;
    int t = threadIdx.x, head = t >> 5, lane = t & 31;
    int beg = g_rowptr[n], end = g_rowptr[n+1];
    int deg = end - beg;
    int cached = deg < CAP ? deg : CAP;
    for (int j = t; j < cached; j += 96) sSrc[j] = g_srcs[beg + j];
    __syncthreads();

    float er_n = g_er[n*HH + head];
    float mx = -1e30f;
    for (int j = lane; j < deg; j += 32) {
        int s = (j < CAP) ? sSrc[j] : g_srcs[beg + j];
        float v = g_el[s*HH + head] + er_n;
        v = v > 0.f ? v : 0.2f*v;
        if (j < CAP) sE[head][j] = v;
        mx = fmaxf(mx, v);
    }
    #pragma unroll
    for (int o = 16; o; o >>= 1) mx = fmaxf(mx, __shfl_xor_sync(0xffffffffu, mx, o));
    float sum = 0.f;
    for (int j = lane; j < deg; j += 32) {
        float v;
        if (j < CAP) v = sE[head][j];
        else {
            int s = g_srcs[beg + j];
            v = g_el[s*HH + head] + er_n;
            v = v > 0.f ? v : 0.2f*v;
        }
        float e = expf(v - mx);
        if (j < CAP) sE[head][j] = e;
        sum += e;
    }
    #pragma unroll
    for (int o = 16; o; o >>= 1) sum += __shfl_xor_sync(0xffffffffu, sum, o);
    float inv = 1.f / (sum + 1e-9f);
    __syncwarp();

    const __half* hb = &g_h[head*HIDN + lane*4];
    float4 a = make_float4(0.f, 0.f, 0.f, 0.f);
    int jn = 0;
    for (; jn + 1 < cached; jn += 2) {
        int   s0 = sSrc[jn],      s1 = sSrc[jn+1];
        float w0 = sE[head][jn],  w1 = sE[head][jn+1];
        uint2 u0 = *(const uint2*)&hb[(size_t)s0*HF];
        uint2 u1 = *(const uint2*)&hb[(size_t)s1*HF];
        float2 p00 = __half22float2(*reinterpret_cast<__half2*>(&u0.x));
        float2 p01 = __half22float2(*reinterpret_cast<__half2*>(&u0.y));
        float2 p10 = __half22float2(*reinterpret_cast<__half2*>(&u1.x));
        float2 p11 = __half22float2(*reinterpret_cast<__half2*>(&u1.y));
        a.x += w0*p00.x + w1*p10.x;
        a.y += w0*p00.y + w1*p10.y;
        a.z += w0*p01.x + w1*p11.x;
        a.w += w0*p01.y + w1*p11.y;
    }
    for (; jn < cached; jn++) {
        int s = sSrc[jn];
        float w = sE[head][jn];
        uint2 u = *(const uint2*)&hb[(size_t)s*HF];
        float2 p0 = __half22float2(*reinterpret_cast<__half2*>(&u.x));
        float2 p1 = __half22float2(*reinterpret_cast<__half2*>(&u.y));
        a.x += w*p0.x; a.y += w*p0.y; a.z += w*p1.x; a.w += w*p1.y;
    }
    for (int j = beg + CAP; j < end; j++) {      // rare fallback
        int s = g_srcs[j];
        float v = g_el[s*HH + head] + er_n;
        v = v > 0.f ? v : 0.2f*v;
        float w = expf(v - mx);
        uint2 u = *(const uint2*)&hb[(size_t)s*HF];
        float2 p0 = __half22float2(*reinterpret_cast<__half2*>(&u.x));
        float2 p1 = __half22float2(*reinterpret_cast<__half2*>(&u.y));
        a.x += w*p0.x; a.y += w*p0.y; a.z += w*p1.x; a.w += w*p1.y;
    }

    const float4 b4 = *(const float4*)&bias[head*HIDN + lane*4];
    a.x = a.x*inv + b4.x;  a.y = a.y*inv + b4.y;
    a.z = a.z*inv + b4.z;  a.w = a.w*inv + b4.w;
    a.x = a.x > 0.f ? a.x : 0.01f*a.x;
    a.y = a.y > 0.f ? a.y : 0.01f*a.y;
    a.z = a.z > 0.f ? a.z : 0.01f*a.z;
    a.w = a.w > 0.f ? a.w : 0.01f*a.w;
    sh4[head][lane] = a;
    __syncthreads();
    if (t < 32) {
        float4 r0 = sh4[0][t], r1 = sh4[1][t], r2 = sh4[2][t];
        float o[4];
        o[0] = (r0.x + r1.x + r2.x) * (1.f/3.f);
        o[1] = (r0.y + r1.y + r2.y) * (1.f/3.f);
        o[2] = (r0.z + r1.z + r2.z) * (1.f/3.f);
        o[3] = (r0.w + r1.w + r2.w) * (1.f/3.f);
        uint32_t lo01, lo23;
        uint32_t hi01 = bfpack2(o[0], o[1], lo01);
        uint32_t hi23 = bfpack2(o[2], o[3], lo23);
        int a0 = frag_addr(n, t*4);
        int a2 = frag_addr(n, t*4 + 2);
        fragOut[a0]       = hi01;
        fragOut[a0 + 128] = lo01;
        fragOut[a2]       = hi23;
        fragOut[a2 + 128] = lo23;
    }
}

// ---------------- classifier: (N,128)@(128,6)+b, warp per node -----------
__global__ void classifier_kernel(const float* __restrict__ lw5, const float* __restrict__ lb5,
                                  float* __restrict__ out)
{
    int gw   = (blockIdx.x*blockDim.x + threadIdx.x) >> 5;
    int lane = threadIdx.x & 31;
    if (gw >= NN) return;
    const float* xr = &g_x[(size_t)gw*HIDN];
    float acc[NCLS] = {};
    #pragma unroll
    for (int k = lane; k < HIDN; k += 32) {
        float xv = xr[k];
        #pragma unroll
        for (int c = 0; c < NCLS; c++) acc[c] += xv * __ldg(&lw5[k*NCLS + c]);
    }
    #pragma unroll
    for (int c = 0; c < NCLS; c++)
        #pragma unroll
        for (int o = 16; o; o >>= 1) acc[c] += __shfl_xor_sync(0xffffffffu, acc[c], o);
    if (lane == 0) {
        #pragma unroll
        for (int c = 0; c < NCLS; c++) out[gw*NCLS + c] = acc[c] + lb5[c];
    }
}

// -------------------------------------------------------------------------
extern "C" void kernel_launch(void* const* d_in, const int* in_sizes, int n_in,
                              void* d_out, int out_size)
{
    const float* in_feat = (const float*)d_in[0];
    const int*   src     = (const int*)  d_in[1];
    const int*   dst     = (const int*)  d_in[2];
    const float* W1  = (const float*)d_in[3];
    const float* al1 = (const float*)d_in[4];
    const float* ar1 = (const float*)d_in[5];
    const float* b1  = (const float*)d_in[6];
    const float* W2  = (const float*)d_in[7];
    const float* al2 = (const float*)d_in[8];
    const float* ar2 = (const float*)d_in[9];
    const float* b2  = (const float*)d_in[10];
    const float* lw1 = (const float*)d_in[11];
    const float* lb1 = (const float*)d_in[12];
    const float* lw2 = (const float*)d_in[13];
    const float* lb2 = (const float*)d_in[14];
    const float* lw3 = (const float*)d_in[15];
    const float* lb3 = (const float*)d_in[16];
    const float* lw4 = (const float*)d_in[17];
    const float* lb4 = (const float*)d_in[18];
    const float* lw5 = (const float*)d_in[19];
    const float* lb5 = (const float*)d_in[20];
    float* out = (float*)d_out;

    uint32_t *pwf, *pfA, *pfB;
    float *px;
    cudaGetSymbolAddress((void**)&pwf, g_wf);
    cudaGetSymbolAddress((void**)&pfA, g_afragA);
    cudaGetSymbolAddress((void**)&pfB, g_afragB);
    cudaGetSymbolAddress((void**)&px,  g_x);

    const int TB = 256;
    dim3 g_gat(HF/128, MBLKS);     // (3, 391)
    dim3 g_mlp(1, MBLKS);

    // pre-splits first (gemm1 stays the 4th launch for ncu)
    presplit_w_kernel<<<(81920 + TB - 1)/TB, TB>>>(W1, W2, lw1, lw2, lw3, lw4);
    presplit_a_kernel<<<(MBLKS*128*64 + TB - 1)/TB, TB>>>(in_feat);
    zero_deg_kernel<<<(NN + TB - 1)/TB, TB>>>();

    // ---- GAT layer 1 GEMM (independent of CSR build) ----
    gemm_kernel<0><<<g_gat, 256>>>(pfA, pwf + WF_W1, nullptr, nullptr, nullptr, NN, al1, ar1);

    // CSR build
    hist_kernel<<<(EE + TB - 1)/TB, TB>>>(dst);
    scan_kernel<<<1, 1024>>>();
    scatter_kernel<<<(EE + TB - 1)/TB, TB>>>(src, dst);

    // ---- GAT layer 1 edge phase ----
    agg_kernel<<<NN, 96>>>(b1, pfA);

    // ---- GAT layer 2 ----
    gemm_kernel<0><<<g_gat, 256>>>(pfA, pwf + WF_W2, nullptr, nullptr, nullptr, NN, al2, ar2);
    agg_kernel<<<NN, 96>>>(b2, pfA);

    // ---- MLP head: frag -> frag chain ----
    gemm_kernel<1><<<g_mlp, 256>>>(pfA, pwf + WF_L1, lb1, nullptr, pfB, NN, nullptr, nullptr);
    gemm_kernel<1><<<g_mlp, 256>>>(pfB, pwf + WF_L2, lb2, nullptr, pfA, NN, nullptr, nullptr);
    gemm_kernel<1><<<g_mlp, 256>>>(pfA, pwf + WF_L3, lb3, nullptr, pfB, NN, nullptr, nullptr);
    gemm_kernel<2><<<g_mlp, 256>>>(pfB, pwf + WF_L4, lb4, px, nullptr, NN, nullptr, nullptr);
    classifier_kernel<<<(NN + 7)/8, 256>>>(lw5, lb5, out);
}

// round 10
// speedup vs baseline: 1.5759x; 1.0714x over previous
#include <cuda_runtime.h>
#include <cuda_bf16.h>
#include <cuda_fp16.h>
#include <cstdint>

#define NN 50000
#define EE 800000
#define HH 3
#define HIDN 128
#define HF (HH*HIDN)   // 384
#define NCLS 6
#define MBLKS 391      // ceil(50000/128)
#define CAP 128        // per-node cached-edge capacity in fused agg kernel
#define FRAGW (MBLKS*16384)

// weight-fragment scratch offsets (words); bf16 hi/lo packed 2-per-word
#define WF_W1  0
#define WF_W2  49152
#define WF_L1  98304
#define WF_L2  114688
#define WF_L3  131072
#define WF_L4  147456
#define WF_TOT 163840

// ---------------- scratch (device globals; no allocation allowed) --------
__device__ __half   g_h[NN*HF];     // post-GEMM per-head features (fp16)
__device__ float    g_x[NN*HIDN];   // classifier input
__device__ float    g_el[NN*HH];
__device__ float    g_er[NN*HH];
__device__ int      g_srcs[EE];     // src node id in CSR order
__device__ int      g_deg[NN];
__device__ int      g_rowptr[NN+1];
__device__ int      g_wptr[NN];
__device__ uint32_t g_wf[WF_TOT];   // pre-split bf16 weight frags
__device__ uint32_t g_afragA[FRAGW];

// ---------------- helpers -------------------------------------------------
__device__ __forceinline__ uint32_t bfpack2(float e0, float e1, uint32_t& loW) {
    __nv_bfloat16 h0 = __float2bfloat16_rn(e0);
    __nv_bfloat16 h1 = __float2bfloat16_rn(e1);
    float r0 = e0 - __bfloat162float(h0);
    float r1 = e1 - __bfloat162float(h1);
    __nv_bfloat16 l0 = __float2bfloat16_rn(r0);
    __nv_bfloat16 l1 = __float2bfloat16_rn(r1);
    loW = (uint32_t)__bfloat16_as_ushort(l0) | ((uint32_t)__bfloat16_as_ushort(l1) << 16);
    return (uint32_t)__bfloat16_as_ushort(h0) | ((uint32_t)__bfloat16_as_ushort(h1) << 16);
}
__device__ __forceinline__ void mma16(float* c, const uint32_t* a, uint32_t b0, uint32_t b1) {
    asm("mma.sync.aligned.m16n8k16.row.col.f32.bf16.bf16.f32 "
        "{%0,%1,%2,%3}, {%4,%5,%6,%7}, {%8,%9}, {%0,%1,%2,%3};"
        : "+f"(c[0]), "+f"(c[1]), "+f"(c[2]), "+f"(c[3])
        : "r"(a[0]), "r"(a[1]), "r"(a[2]), "r"(a[3]), "r"(b0), "r"(b1));
}
// A-fragment word address (hi plane; lo at +128) for element (row, k even)
__device__ __forceinline__ int frag_addr(int row, int k) {
    int mblk = row >> 7, ch = k >> 4, mtile = (row >> 4) & 7;
    int r16 = row & 15, k16 = k & 15;
    int reg  = (k16 >> 3)*2 + (r16 >> 3);
    int lane = (r16 & 7)*4 + ((k16 >> 1) & 3);
    return ((mblk*8 + ch)*8 + mtile)*256 + lane*4 + reg;
}
__device__ __forceinline__ uint4 ldg4(const uint32_t* p) {
    return *reinterpret_cast<const uint4*>(p);
}
// 12-mma bf16x3 step for one (nA,nB) B pair
__device__ __forceinline__ void mma_step(float acc[2][8][4], const uint4 ah[2],
                                         const uint4 alo[2], uint4 b0, uint4 b1,
                                         int nA, int nB)
{
    mma16(acc[0][nA], (const uint32_t*)&ah[0],  b0.x, b0.y);
    mma16(acc[1][nA], (const uint32_t*)&ah[1],  b0.x, b0.y);
    mma16(acc[0][nB], (const uint32_t*)&ah[0],  b1.x, b1.y);
    mma16(acc[1][nB], (const uint32_t*)&ah[1],  b1.x, b1.y);
    mma16(acc[0][nA], (const uint32_t*)&ah[0],  b0.z, b0.w);
    mma16(acc[1][nA], (const uint32_t*)&ah[1],  b0.z, b0.w);
    mma16(acc[0][nB], (const uint32_t*)&ah[0],  b1.z, b1.w);
    mma16(acc[1][nB], (const uint32_t*)&ah[1],  b1.z, b1.w);
    mma16(acc[0][nA], (const uint32_t*)&alo[0], b0.x, b0.y);
    mma16(acc[1][nA], (const uint32_t*)&alo[1], b0.x, b0.y);
    mma16(acc[0][nB], (const uint32_t*)&alo[0], b1.x, b1.y);
    mma16(acc[1][nB], (const uint32_t*)&alo[1], b1.x, b1.y);
}

// ---------------- pre-split kernels --------------------------------------
__global__ void presplit_w_kernel(const float* __restrict__ W1, const float* __restrict__ W2,
                                  const float* __restrict__ L1, const float* __restrict__ L2,
                                  const float* __restrict__ L3, const float* __restrict__ L4)
{
    int i = blockIdx.x*blockDim.x + threadIdx.x;
    if (i >= 81920) return;
    const float* W; int ncols, ooff, rem;
    if      (i < 24576) { W = W1; ncols = 384; ooff = WF_W1; rem = i; }
    else if (i < 49152) { W = W2; ncols = 384; ooff = WF_W2; rem = i - 24576; }
    else if (i < 57344) { W = L1; ncols = 128; ooff = WF_L1; rem = i - 49152; }
    else if (i < 65536) { W = L2; ncols = 128; ooff = WF_L2; rem = i - 57344; }
    else if (i < 73728) { W = L3; ncols = 128; ooff = WF_L3; rem = i - 65536; }
    else                { W = L4; ncols = 128; ooff = WF_L4; rem = i - 73728; }
    int g = rem >> 6, idx = rem & 63;
    int lane = idx >> 1, reg = idx & 1;
    int nt = g & 7, wn = (g >> 3) & 1, ch = (g >> 4) & 7, cb = g >> 7;
    int k = ch*16 + reg*8 + (lane & 3)*2;
    int n = cb*128 + wn*64 + nt*8 + (lane >> 2);
    float e0 = W[k*ncols + n];
    float e1 = W[(k+1)*ncols + n];
    uint32_t loW;
    uint32_t hiW = bfpack2(e0, e1, loW);
    g_wf[ooff + g*128 + lane*4 + reg]     = hiW;
    g_wf[ooff + g*128 + lane*4 + 2 + reg] = loW;
}

__global__ void presplit_a_kernel(const float* __restrict__ X)
{
    int i = blockIdx.x*blockDim.x + threadIdx.x;
    if (i >= MBLKS*128*64) return;
    int row = i >> 6, k = (i & 63)*2;
    float e0 = 0.f, e1 = 0.f;
    if (row < NN) {
        e0 = X[row*128 + k];
        e1 = X[row*128 + k + 1];
    }
    uint32_t loW;
    uint32_t hiW = bfpack2(e0, e1, loW);
    int a = frag_addr(row, k);
    g_afragA[a]       = hiW;
    g_afragA[a + 128] = loW;
}

// ---------------- CSR build ----------------------------------------------
__global__ void zero_deg_kernel() {
    int i = blockIdx.x*blockDim.x + threadIdx.x;
    if (i < NN) g_deg[i] = 0;
}

__global__ void hist_kernel(const int* __restrict__ dst) {
    int i = blockIdx.x*blockDim.x + threadIdx.x;
    if (i < EE) atomicAdd(&g_deg[dst[i]], 1);
}

__global__ void scan_kernel() {
    __shared__ int sh[1024];
    int t = threadIdx.x;
    const int ITEMS = (NN + 1023) / 1024;
    int base = t * ITEMS;
    int s = 0;
    for (int i = 0; i < ITEMS; i++) {
        int idx = base + i;
        if (idx < NN) s += g_deg[idx];
    }
    sh[t] = s;
    __syncthreads();
    for (int off = 1; off < 1024; off <<= 1) {
        int v = (t >= off) ? sh[t - off] : 0;
        __syncthreads();
        sh[t] += v;
        __syncthreads();
    }
    int run = sh[t] - s;
    for (int i = 0; i < ITEMS; i++) {
        int idx = base + i;
        if (idx < NN) {
            g_rowptr[idx] = run;
            g_wptr[idx]   = run;
            run += g_deg[idx];
        }
    }
    if (t == 0) g_rowptr[NN] = EE;
}

__global__ void scatter_kernel(const int* __restrict__ src, const int* __restrict__ dst) {
    int i = blockIdx.x*blockDim.x + threadIdx.x;
    if (i < EE) {
        int d = dst[i];
        int p = atomicAdd(&g_wptr[d], 1);
        g_srcs[p] = src[i];
    }
}

// ------------- GAT GEMM: bf16x3, smem-free, A register double-buffer -----
// C -> g_h fp16 + attention dots for head hh=blockIdx.x -> g_el/g_er.
__global__ __launch_bounds__(256, 2)
void gatgemm_kernel(const uint32_t* __restrict__ af, const uint32_t* __restrict__ wfp,
                    int M, const float* __restrict__ al, const float* __restrict__ ar)
{
    __shared__ float sEl[2][128], sEr[2][128];
    int tid  = threadIdx.x;
    int lane = tid & 31, warp = tid >> 5;
    int wm = warp >> 1, wn = warp & 1;
    int mblk = blockIdx.y;
    int m0 = mblk*128, col0 = blockIdx.x*128;

    float acc[2][8][4];
    #pragma unroll
    for (int i = 0; i < 2; i++)
        #pragma unroll
        for (int j = 0; j < 8; j++)
            #pragma unroll
            for (int q = 0; q < 4; q++) acc[i][j][q] = 0.f;

    const uint32_t* afb = af  + mblk*16384;
    const uint32_t* wfb = wfp + blockIdx.x*16384;

    uint4 ahN[2], aloN[2];
    #pragma unroll
    for (int mt = 0; mt < 2; mt++) {
        int base = (wm*2 + mt)*256 + lane*4;
        ahN[mt]  = ldg4(&afb[base]);
        aloN[mt] = ldg4(&afb[base + 128]);
    }

    #pragma unroll 1
    for (int ch = 0; ch < 8; ch++) {
        uint4 ah[2]  = {ahN[0], ahN[1]};
        uint4 alo[2] = {aloN[0], aloN[1]};
        if (ch < 7) {     // prefetch next chunk's A before this chunk's mma
            #pragma unroll
            for (int mt = 0; mt < 2; mt++) {
                int base = ((ch+1)*8 + wm*2 + mt)*256 + lane*4;
                ahN[mt]  = ldg4(&afb[base]);
                aloN[mt] = ldg4(&afb[base + 128]);
            }
        }
        #pragma unroll
        for (int ng = 0; ng < 4; ng++) {
            uint4 b0 = ldg4(&wfb[(ch*16 + wn*8 + 2*ng)*128 + lane*4]);
            uint4 b1 = ldg4(&wfb[(ch*16 + wn*8 + 2*ng + 1)*128 + lane*4]);
            mma_step(acc, ah, alo, b0, b1, 2*ng, 2*ng + 1);
        }
    }

    // ---- fp16 h store ----
    #pragma unroll
    for (int mt = 0; mt < 2; mt++) {
        #pragma unroll
        for (int half = 0; half < 2; half++) {
            int r = m0 + wm*32 + mt*16 + (lane >> 2) + half*8;
            if (r >= M) continue;
            #pragma unroll
            for (int nt = 0; nt < 8; nt++) {
                int c = col0 + wn*64 + nt*8 + 2*(lane & 3);
                __half2 hv = __float22half2_rn(
                    make_float2(acc[mt][nt][half*2 + 0], acc[mt][nt][half*2 + 1]));
                *reinterpret_cast<__half2*>(&g_h[(size_t)r*HF + c]) = hv;
            }
        }
    }
    // ---- fused attention dots ----
    int hh = blockIdx.x;
    float alv[8][2], arv[8][2];
    #pragma unroll
    for (int nt = 0; nt < 8; nt++)
        #pragma unroll
        for (int j = 0; j < 2; j++) {
            int c = wn*64 + nt*8 + 2*(lane & 3) + j;
            alv[nt][j] = __ldg(&al[hh*HIDN + c]);
            arv[nt][j] = __ldg(&ar[hh*HIDN + c]);
        }
    #pragma unroll
    for (int mt = 0; mt < 2; mt++) {
        #pragma unroll
        for (int half = 0; half < 2; half++) {
            float pl = 0.f, pr = 0.f;
            #pragma unroll
            for (int nt = 0; nt < 8; nt++)
                #pragma unroll
                for (int j = 0; j < 2; j++) {
                    float v = acc[mt][nt][half*2 + j];
                    pl += v * alv[nt][j];
                    pr += v * arv[nt][j];
                }
            pl += __shfl_xor_sync(0xffffffffu, pl, 1);
            pl += __shfl_xor_sync(0xffffffffu, pl, 2);
            pr += __shfl_xor_sync(0xffffffffu, pr, 1);
            pr += __shfl_xor_sync(0xffffffffu, pr, 2);
            if ((lane & 3) == 0) {
                int rl = wm*32 + mt*16 + (lane >> 2) + half*8;
                sEl[wn][rl] = pl;
                sEr[wn][rl] = pr;
            }
        }
    }
    __syncthreads();
    if (tid < 128) {
        int r = m0 + tid;
        if (r < M) {
            g_el[r*HH + hh] = sEl[0][tid] + sEl[1][tid];
            g_er[r*HH + hh] = sEr[0][tid] + sEr[1][tid];
        }
    }
}

// ------------- fused MLP: lin1..lin4 in one kernel, frags via smem -------
__global__ __launch_bounds__(256, 2)
void mlp_kernel(const uint32_t* __restrict__ af, const uint32_t* __restrict__ wfbase,
                const float* __restrict__ lb1, const float* __restrict__ lb2,
                const float* __restrict__ lb3, const float* __restrict__ lb4,
                float* __restrict__ xout, int M)
{
    extern __shared__ uint32_t sF[];   // 16384 words = 64 KB
    int tid  = threadIdx.x;
    int lane = tid & 31, warp = tid >> 5;
    int wm = warp >> 1, wn = warp & 1;
    int mblk = blockIdx.x;
    int m0 = mblk*128;

    const float* midbias[3] = {lb1, lb2, lb3};
    const int woff[4] = {WF_L1, WF_L2, WF_L3, WF_L4};

    float acc[2][8][4];
    #pragma unroll
    for (int i = 0; i < 2; i++)
        #pragma unroll
        for (int j = 0; j < 8; j++)
            #pragma unroll
            for (int q = 0; q < 4; q++) acc[i][j][q] = 0.f;

    // ---- layer 1: A from global frags ----
    {
        const uint32_t* afb = af + mblk*16384;
        const uint32_t* wfl = wfbase + woff[0];
        #pragma unroll 1
        for (int ch = 0; ch < 8; ch++) {
            uint4 ah[2], alo[2];
            #pragma unroll
            for (int mt = 0; mt < 2; mt++) {
                int base = (ch*8 + wm*2 + mt)*256 + lane*4;
                ah[mt]  = ldg4(&afb[base]);
                alo[mt] = ldg4(&afb[base + 128]);
            }
            #pragma unroll
            for (int ng = 0; ng < 4; ng++) {
                uint4 b0 = ldg4(&wfl[(ch*16 + wn*8 + 2*ng)*128 + lane*4]);
                uint4 b1 = ldg4(&wfl[(ch*16 + wn*8 + 2*ng + 1)*128 + lane*4]);
                mma_step(acc, ah, alo, b0, b1, 2*ng, 2*ng + 1);
            }
        }
    }

    // ---- layers 2..4: frag exchange via smem ----
    #pragma unroll 1
    for (int l = 1; l < 4; l++) {
        const float* bias = midbias[l-1];
        // convert acc (+bias, leaky) -> smem frags; zero acc
        #pragma unroll
        for (int mt = 0; mt < 2; mt++) {
            #pragma unroll
            for (int ng = 0; ng < 4; ng++) {
                int ntE = 2*ng, ntO = 2*ng + 1;
                int cE = wn*64 + ntE*8 + 2*(lane & 3);
                float bE0 = bias[cE],     bE1 = bias[cE + 1];
                float bO0 = bias[cE + 8], bO1 = bias[cE + 9];
                float e0 = acc[mt][ntE][0] + bE0, e1 = acc[mt][ntE][1] + bE1;
                float e2 = acc[mt][ntE][2] + bE0, e3 = acc[mt][ntE][3] + bE1;
                float o0 = acc[mt][ntO][0] + bO0, o1 = acc[mt][ntO][1] + bO1;
                float o2 = acc[mt][ntO][2] + bO0, o3 = acc[mt][ntO][3] + bO1;
                e0 = e0 > 0.f ? e0 : 0.01f*e0;  e1 = e1 > 0.f ? e1 : 0.01f*e1;
                e2 = e2 > 0.f ? e2 : 0.01f*e2;  e3 = e3 > 0.f ? e3 : 0.01f*e3;
                o0 = o0 > 0.f ? o0 : 0.01f*o0;  o1 = o1 > 0.f ? o1 : 0.01f*o1;
                o2 = o2 > 0.f ? o2 : 0.01f*o2;  o3 = o3 > 0.f ? o3 : 0.01f*o3;
                uint32_t l0, l1, l2, l3;
                uint32_t h0 = bfpack2(e0, e1, l0);
                uint32_t h1 = bfpack2(e2, e3, l1);
                uint32_t h2 = bfpack2(o0, o1, l2);
                uint32_t h3 = bfpack2(o2, o3, l3);
                int base = ((wn*4 + ng)*8 + wm*2 + mt)*256 + lane*4;
                *reinterpret_cast<uint4*>(&sF[base])       = make_uint4(h0, h1, h2, h3);
                *reinterpret_cast<uint4*>(&sF[base + 128]) = make_uint4(l0, l1, l2, l3);
                #pragma unroll
                for (int q = 0; q < 4; q++) { acc[mt][ntE][q] = 0.f; acc[mt][ntO][q] = 0.f; }
            }
        }
        __syncthreads();
        const uint32_t* wfl = wfbase + woff[l];
        #pragma unroll 1
        for (int ch = 0; ch < 8; ch++) {
            uint4 ah[2], alo[2];
            #pragma unroll
            for (int mt = 0; mt < 2; mt++) {
                int base = (ch*8 + wm*2 + mt)*256 + lane*4;
                ah[mt]  = *reinterpret_cast<const uint4*>(&sF[base]);
                alo[mt] = *reinterpret_cast<const uint4*>(&sF[base + 128]);
            }
            #pragma unroll
            for (int ng = 0; ng < 4; ng++) {
                uint4 b0 = ldg4(&wfl[(ch*16 + wn*8 + 2*ng)*128 + lane*4]);
                uint4 b1 = ldg4(&wfl[(ch*16 + wn*8 + 2*ng + 1)*128 + lane*4]);
                mma_step(acc, ah, alo, b0, b1, 2*ng, 2*ng + 1);
            }
        }
        __syncthreads();   // reads done before next conversion overwrites
    }

    // ---- final: bias lb4 + leaky -> g_x fp32 ----
    #pragma unroll
    for (int mt = 0; mt < 2; mt++) {
        #pragma unroll
        for (int half = 0; half < 2; half++) {
            int r = m0 + wm*32 + mt*16 + (lane >> 2) + half*8;
            if (r >= M) continue;
            #pragma unroll
            for (int nt = 0; nt < 8; nt++) {
                int c = wn*64 + nt*8 + 2*(lane & 3);
                float v0 = acc[mt][nt][half*2 + 0] + lb4[c];
                float v1 = acc[mt][nt][half*2 + 1] + lb4[c + 1];
                v0 = v0 > 0.f ? v0 : 0.01f*v0;
                v1 = v1 > 0.f ? v1 : 0.01f*v1;
                *(float2*)&xout[(size_t)r*HIDN + c] = make_float2(v0, v1);
            }
        }
    }
}

// ---- fused softmax + aggregation, block (96 thr) per node ---------------
__global__ __launch_bounds__(96)
void agg_kernel(const float* __restrict__ bias, uint32_t* __restrict__ fragOut)
{
    __shared__ int    sSrc[CAP];
    __shared__ float  sE[3][CAP];
    __shared__ float4 sh4[3][32];
    int n = blockIdx.x;
    int t = threadIdx.x, head = t >> 5, lane = t & 31;
    int beg = g_rowptr[n], end = g_rowptr[n+1];
    int deg = end - beg;
    int cached = deg < CAP ? deg : CAP;
    for (int j = t; j < cached; j += 96) sSrc[j] = g_srcs[beg + j];
    __syncthreads();

    float er_n = g_er[n*HH + head];
    float mx = -1e30f;
    for (int j = lane; j < deg; j += 32) {
        int s = (j < CAP) ? sSrc[j] : g_srcs[beg + j];
        float v = g_el[s*HH + head] + er_n;
        v = v > 0.f ? v : 0.2f*v;
        if (j < CAP) sE[head][j] = v;
        mx = fmaxf(mx, v);
    }
    #pragma unroll
    for (int o = 16; o; o >>= 1) mx = fmaxf(mx, __shfl_xor_sync(0xffffffffu, mx, o));
    float sum = 0.f;
    for (int j = lane; j < deg; j += 32) {
        float v;
        if (j < CAP) v = sE[head][j];
        else {
            int s = g_srcs[beg + j];
            v = g_el[s*HH + head] + er_n;
            v = v > 0.f ? v : 0.2f*v;
        }
        float e = expf(v - mx);
        if (j < CAP) sE[head][j] = e;
        sum += e;
    }
    #pragma unroll
    for (int o = 16; o; o >>= 1) sum += __shfl_xor_sync(0xffffffffu, sum, o);
    float inv = 1.f / (sum + 1e-9f);
    __syncwarp();

    const __half* hb = &g_h[head*HIDN + lane*4];
    float4 a = make_float4(0.f, 0.f, 0.f, 0.f);
    int jn = 0;
    for (; jn + 1 < cached; jn += 2) {
        int   s0 = sSrc[jn],      s1 = sSrc[jn+1];
        float w0 = sE[head][jn],  w1 = sE[head][jn+1];
        uint2 u0 = *(const uint2*)&hb[(size_t)s0*HF];
        uint2 u1 = *(const uint2*)&hb[(size_t)s1*HF];
        float2 p00 = __half22float2(*reinterpret_cast<__half2*>(&u0.x));
        float2 p01 = __half22float2(*reinterpret_cast<__half2*>(&u0.y));
        float2 p10 = __half22float2(*reinterpret_cast<__half2*>(&u1.x));
        float2 p11 = __half22float2(*reinterpret_cast<__half2*>(&u1.y));
        a.x += w0*p00.x + w1*p10.x;
        a.y += w0*p00.y + w1*p10.y;
        a.z += w0*p01.x + w1*p11.x;
        a.w += w0*p01.y + w1*p11.y;
    }
    for (; jn < cached; jn++) {
        int s = sSrc[jn];
        float w = sE[head][jn];
        uint2 u = *(const uint2*)&hb[(size_t)s*HF];
        float2 p0 = __half22float2(*reinterpret_cast<__half2*>(&u.x));
        float2 p1 = __half22float2(*reinterpret_cast<__half2*>(&u.y));
        a.x += w*p0.x; a.y += w*p0.y; a.z += w*p1.x; a.w += w*p1.y;
    }
    for (int j = beg + CAP; j < end; j++) {      // rare fallback
        int s = g_srcs[j];
        float v = g_el[s*HH + head] + er_n;
        v = v > 0.f ? v : 0.2f*v;
        float w = expf(v - mx);
        uint2 u = *(const uint2*)&hb[(size_t)s*HF];
        float2 p0 = __half22float2(*reinterpret_cast<__half2*>(&u.x));
        float2 p1 = __half22float2(*reinterpret_cast<__half2*>(&u.y));
        a.x += w*p0.x; a.y += w*p0.y; a.z += w*p1.x; a.w += w*p1.y;
    }

    const float4 b4 = *(const float4*)&bias[head*HIDN + lane*4];
    a.x = a.x*inv + b4.x;  a.y = a.y*inv + b4.y;
    a.z = a.z*inv + b4.z;  a.w = a.w*inv + b4.w;
    a.x = a.x > 0.f ? a.x : 0.01f*a.x;
    a.y = a.y > 0.f ? a.y : 0.01f*a.y;
    a.z = a.z > 0.f ? a.z : 0.01f*a.z;
    a.w = a.w > 0.f ? a.w : 0.01f*a.w;
    sh4[head][lane] = a;
    __syncthreads();
    if (t < 32) {
        float4 r0 = sh4[0][t], r1 = sh4[1][t], r2 = sh4[2][t];
        float o[4];
        o[0] = (r0.x + r1.x + r2.x) * (1.f/3.f);
        o[1] = (r0.y + r1.y + r2.y) * (1.f/3.f);
        o[2] = (r0.z + r1.z + r2.z) * (1.f/3.f);
        o[3] = (r0.w + r1.w + r2.w) * (1.f/3.f);
        uint32_t lo01, lo23;
        uint32_t hi01 = bfpack2(o[0], o[1], lo01);
        uint32_t hi23 = bfpack2(o[2], o[3], lo23);
        int a0 = frag_addr(n, t*4);
        int a2 = frag_addr(n, t*4 + 2);
        fragOut[a0]       = hi01;
        fragOut[a0 + 128] = lo01;
        fragOut[a2]       = hi23;
        fragOut[a2 + 128] = lo23;
    }
}

// ---------------- classifier: (N,128)@(128,6)+b, warp per node -----------
__global__ void classifier_kernel(const float* __restrict__ lw5, const float* __restrict__ lb5,
                                  float* __restrict__ out)
{
    int gw   = (blockIdx.x*blockDim.x + threadIdx.x) >> 5;
    int lane = threadIdx.x & 31;
    if (gw >= NN) return;
    const float* xr = &g_x[(size_t)gw*HIDN];
    float acc[NCLS] = {};
    #pragma unroll
    for (int k = lane; k < HIDN; k += 32) {
        float xv = xr[k];
        #pragma unroll
        for (int c = 0; c < NCLS; c++) acc[c] += xv * __ldg(&lw5[k*NCLS + c]);
    }
    #pragma unroll
    for (int c = 0; c < NCLS; c++)
        #pragma unroll
        for (int o = 16; o; o >>= 1) acc[c] += __shfl_xor_sync(0xffffffffu, acc[c], o);
    if (lane == 0) {
        #pragma unroll
        for (int c = 0; c < NCLS; c++) out[gw*NCLS + c] = acc[c] + lb5[c];
    }
}

// -------------------------------------------------------------------------
extern "C" void kernel_launch(void* const* d_in, const int* in_sizes, int n_in,
                              void* d_out, int out_size)
{
    const float* in_feat = (const float*)d_in[0];
    const int*   src     = (const int*)  d_in[1];
    const int*   dst     = (const int*)  d_in[2];
    const float* W1  = (const float*)d_in[3];
    const float* al1 = (const float*)d_in[4];
    const float* ar1 = (const float*)d_in[5];
    const float* b1  = (const float*)d_in[6];
    const float* W2  = (const float*)d_in[7];
    const float* al2 = (const float*)d_in[8];
    const float* ar2 = (const float*)d_in[9];
    const float* b2  = (const float*)d_in[10];
    const float* lw1 = (const float*)d_in[11];
    const float* lb1 = (const float*)d_in[12];
    const float* lw2 = (const float*)d_in[13];
    const float* lb2 = (const float*)d_in[14];
    const float* lw3 = (const float*)d_in[15];
    const float* lb3 = (const float*)d_in[16];
    const float* lw4 = (const float*)d_in[17];
    const float* lb4 = (const float*)d_in[18];
    const float* lw5 = (const float*)d_in[19];
    const float* lb5 = (const float*)d_in[20];
    float* out = (float*)d_out;

    uint32_t *pwf, *pfA;
    float *px;
    cudaGetSymbolAddress((void**)&pwf, g_wf);
    cudaGetSymbolAddress((void**)&pfA, g_afragA);
    cudaGetSymbolAddress((void**)&px,  g_x);

    cudaFuncSetAttribute(mlp_kernel, cudaFuncAttributeMaxDynamicSharedMemorySize, 65536);

    const int TB = 256;
    dim3 g_gat(HF/128, MBLKS);     // (3, 391)

    // pre-splits first (gatgemm stays the 4th launch for ncu)
    presplit_w_kernel<<<(81920 + TB - 1)/TB, TB>>>(W1, W2, lw1, lw2, lw3, lw4);
    presplit_a_kernel<<<(MBLKS*128*64 + TB - 1)/TB, TB>>>(in_feat);
    zero_deg_kernel<<<(NN + TB - 1)/TB, TB>>>();

    // ---- GAT layer 1 GEMM (independent of CSR build) ----
    gatgemm_kernel<<<g_gat, 256>>>(pfA, pwf + WF_W1, NN, al1, ar1);

    // CSR build
    hist_kernel<<<(EE + TB - 1)/TB, TB>>>(dst);
    scan_kernel<<<1, 1024>>>();
    scatter_kernel<<<(EE + TB - 1)/TB, TB>>>(src, dst);

    // ---- GAT layer 1 edge phase ----
    agg_kernel<<<NN, 96>>>(b1, pfA);

    // ---- GAT layer 2 ----
    gatgemm_kernel<<<g_gat, 256>>>(pfA, pwf + WF_W2, NN, al2, ar2);
    agg_kernel<<<NN, 96>>>(b2, pfA);

    // ---- fused MLP (lin1..lin4) ----
    mlp_kernel<<<MBLKS, 256, 65536>>>(pfA, pwf, lb1, lb2, lb3, lb4, px, NN);
    classifier_kernel<<<(NN + 7)/8, 256>>>(lw5, lb5, out);
}

// round 11
// speedup vs baseline: 1.6405x; 1.0410x over previous
#include <cuda_runtime.h>
#include <cuda_bf16.h>
#include <cuda_fp16.h>
#include <cstdint>

#define NN 50000
#define EE 800000
#define HH 3
#define HIDN 128
#define HF (HH*HIDN)   // 384
#define NCLS 6
#define MBLKS 391      // ceil(50000/128)
#define CAP 128        // per-node cached-edge capacity in fused agg kernel
#define FRAGW (MBLKS*16384)

// weight-fragment scratch offsets (words); bf16 hi/lo packed 2-per-word
#define WF_W1  0
#define WF_W2  49152
#define WF_L1  98304
#define WF_L2  114688
#define WF_L3  131072
#define WF_L4  147456
#define WF_TOT 163840

// ---------------- scratch (device globals; no allocation allowed) --------
__device__ __half   g_h[NN*HF];     // post-GEMM per-head features (fp16)
__device__ float    g_x[NN*HIDN];   // classifier input
__device__ float    g_el[NN*HH];
__device__ float    g_er[NN*HH];
__device__ int      g_srcs[EE];     // src node id in CSR order
__device__ int      g_deg[NN];
__device__ int      g_rowptr[NN+1];
__device__ int      g_wptr[NN];
__device__ uint32_t g_wf[WF_TOT];   // pre-split bf16 weight frags
__device__ uint32_t g_afragA[FRAGW];

// ---------------- helpers -------------------------------------------------
__device__ __forceinline__ uint32_t bfpack2(float e0, float e1, uint32_t& loW) {
    __nv_bfloat16 h0 = __float2bfloat16_rn(e0);
    __nv_bfloat16 h1 = __float2bfloat16_rn(e1);
    float r0 = e0 - __bfloat162float(h0);
    float r1 = e1 - __bfloat162float(h1);
    __nv_bfloat16 l0 = __float2bfloat16_rn(r0);
    __nv_bfloat16 l1 = __float2bfloat16_rn(r1);
    loW = (uint32_t)__bfloat16_as_ushort(l0) | ((uint32_t)__bfloat16_as_ushort(l1) << 16);
    return (uint32_t)__bfloat16_as_ushort(h0) | ((uint32_t)__bfloat16_as_ushort(h1) << 16);
}
__device__ __forceinline__ void mma16(float* c, const uint32_t* a, uint32_t b0, uint32_t b1) {
    asm("mma.sync.aligned.m16n8k16.row.col.f32.bf16.bf16.f32 "
        "{%0,%1,%2,%3}, {%4,%5,%6,%7}, {%8,%9}, {%0,%1,%2,%3};"
        : "+f"(c[0]), "+f"(c[1]), "+f"(c[2]), "+f"(c[3])
        : "r"(a[0]), "r"(a[1]), "r"(a[2]), "r"(a[3]), "r"(b0), "r"(b1));
}
// A-fragment word address (hi plane; lo at +128) for element (row, k even)
__device__ __forceinline__ int frag_addr(int row, int k) {
    int mblk = row >> 7, ch = k >> 4, mtile = (row >> 4) & 7;
    int r16 = row & 15, k16 = k & 15;
    int reg  = (k16 >> 3)*2 + (r16 >> 3);
    int lane = (r16 & 7)*4 + ((k16 >> 1) & 3);
    return ((mblk*8 + ch)*8 + mtile)*256 + lane*4 + reg;
}
__device__ __forceinline__ uint4 ldg4(const uint32_t* p) {
    return *reinterpret_cast<const uint4*>(p);
}
// 12-mma bf16x3 step for one (nA,nB) B pair
__device__ __forceinline__ void mma_step(float acc[2][8][4], const uint4 ah[2],
                                         const uint4 alo[2], uint4 b0, uint4 b1,
                                         int nA, int nB)
{
    mma16(acc[0][nA], (const uint32_t*)&ah[0],  b0.x, b0.y);
    mma16(acc[1][nA], (const uint32_t*)&ah[1],  b0.x, b0.y);
    mma16(acc[0][nB], (const uint32_t*)&ah[0],  b1.x, b1.y);
    mma16(acc[1][nB], (const uint32_t*)&ah[1],  b1.x, b1.y);
    mma16(acc[0][nA], (const uint32_t*)&ah[0],  b0.z, b0.w);
    mma16(acc[1][nA], (const uint32_t*)&ah[1],  b0.z, b0.w);
    mma16(acc[0][nB], (const uint32_t*)&ah[0],  b1.z, b1.w);
    mma16(acc[1][nB], (const uint32_t*)&ah[1],  b1.z, b1.w);
    mma16(acc[0][nA], (const uint32_t*)&alo[0], b0.x, b0.y);
    mma16(acc[1][nA], (const uint32_t*)&alo[1], b0.x, b0.y);
    mma16(acc[0][nB], (const uint32_t*)&alo[0], b1.x, b1.y);
    mma16(acc[1][nB], (const uint32_t*)&alo[1], b1.x, b1.y);
}

// ---------------- pre-split kernels --------------------------------------
__global__ void presplit_w_kernel(const float* __restrict__ W1, const float* __restrict__ W2,
                                  const float* __restrict__ L1, const float* __restrict__ L2,
                                  const float* __restrict__ L3, const float* __restrict__ L4)
{
    int i = blockIdx.x*blockDim.x + threadIdx.x;
    if (i >= 81920) return;
    const float* W; int ncols, ooff, rem;
    if      (i < 24576) { W = W1; ncols = 384; ooff = WF_W1; rem = i; }
    else if (i < 49152) { W = W2; ncols = 384; ooff = WF_W2; rem = i - 24576; }
    else if (i < 57344) { W = L1; ncols = 128; ooff = WF_L1; rem = i - 49152; }
    else if (i < 65536) { W = L2; ncols = 128; ooff = WF_L2; rem = i - 57344; }
    else if (i < 73728) { W = L3; ncols = 128; ooff = WF_L3; rem = i - 65536; }
    else                { W = L4; ncols = 128; ooff = WF_L4; rem = i - 73728; }
    int g = rem >> 6, idx = rem & 63;
    int lane = idx >> 1, reg = idx & 1;
    int nt = g & 7, wn = (g >> 3) & 1, ch = (g >> 4) & 7, cb = g >> 7;
    int k = ch*16 + reg*8 + (lane & 3)*2;
    int n = cb*128 + wn*64 + nt*8 + (lane >> 2);
    float e0 = W[k*ncols + n];
    float e1 = W[(k+1)*ncols + n];
    uint32_t loW;
    uint32_t hiW = bfpack2(e0, e1, loW);
    g_wf[ooff + g*128 + lane*4 + reg]     = hiW;
    g_wf[ooff + g*128 + lane*4 + 2 + reg] = loW;
}

__global__ void presplit_a_kernel(const float* __restrict__ X)
{
    int i = blockIdx.x*blockDim.x + threadIdx.x;
    if (i >= MBLKS*128*64) return;
    int row = i >> 6, k = (i & 63)*2;
    float e0 = 0.f, e1 = 0.f;
    if (row < NN) {
        e0 = X[row*128 + k];
        e1 = X[row*128 + k + 1];
    }
    uint32_t loW;
    uint32_t hiW = bfpack2(e0, e1, loW);
    int a = frag_addr(row, k);
    g_afragA[a]       = hiW;
    g_afragA[a + 128] = loW;
}

// ---------------- CSR build ----------------------------------------------
__global__ void zero_deg_kernel() {
    int i = blockIdx.x*blockDim.x + threadIdx.x;
    if (i < NN) g_deg[i] = 0;
}

__global__ void hist_kernel(const int* __restrict__ dst) {
    int i = blockIdx.x*blockDim.x + threadIdx.x;
    if (i < EE) atomicAdd(&g_deg[dst[i]], 1);
}

__global__ void scan_kernel() {
    __shared__ int sh[1024];
    int t = threadIdx.x;
    const int ITEMS = (NN + 1023) / 1024;
    int base = t * ITEMS;
    int s = 0;
    for (int i = 0; i < ITEMS; i++) {
        int idx = base + i;
        if (idx < NN) s += g_deg[idx];
    }
    sh[t] = s;
    __syncthreads();
    for (int off = 1; off < 1024; off <<= 1) {
        int v = (t >= off) ? sh[t - off] : 0;
        __syncthreads();
        sh[t] += v;
        __syncthreads();
    }
    int run = sh[t] - s;
    for (int i = 0; i < ITEMS; i++) {
        int idx = base + i;
        if (idx < NN) {
            g_rowptr[idx] = run;
            g_wptr[idx]   = run;
            run += g_deg[idx];
        }
    }
    if (t == 0) g_rowptr[NN] = EE;
}

__global__ void scatter_kernel(const int* __restrict__ src, const int* __restrict__ dst) {
    int i = blockIdx.x*blockDim.x + threadIdx.x;
    if (i < EE) {
        int d = dst[i];
        int p = atomicAdd(&g_wptr[d], 1);
        g_srcs[p] = src[i];
    }
}

// ------------- GAT GEMM: bf16x3, smem-free, B software pipeline ----------
// C -> g_h fp16 + attention dots for head hh=blockIdx.x -> g_el/g_er.
__global__ __launch_bounds__(256, 2)
void gatgemm_kernel(const uint32_t* __restrict__ af, const uint32_t* __restrict__ wfp,
                    int M, const float* __restrict__ al, const float* __restrict__ ar)
{
    __shared__ float sEl[2][128], sEr[2][128];
    int tid  = threadIdx.x;
    int lane = tid & 31, warp = tid >> 5;
    int wm = warp >> 1, wn = warp & 1;
    int mblk = blockIdx.y;
    int m0 = mblk*128, col0 = blockIdx.x*128;

    float acc[2][8][4];
    #pragma unroll
    for (int i = 0; i < 2; i++)
        #pragma unroll
        for (int j = 0; j < 8; j++)
            #pragma unroll
            for (int q = 0; q < 4; q++) acc[i][j][q] = 0.f;

    const uint32_t* afb = af  + mblk*16384;
    const uint32_t* wfw = wfp + blockIdx.x*16384 + wn*8*128 + lane*4;

    // B pipeline: (b0,b1) for pair (ch=0, ng=0) preloaded
    uint4 b0 = ldg4(wfw);
    uint4 b1 = ldg4(wfw + 128);

    #pragma unroll 1
    for (int ch = 0; ch < 8; ch++) {
        uint4 ah[2], alo[2];
        #pragma unroll
        for (int mt = 0; mt < 2; mt++) {
            int base = (ch*8 + wm*2 + mt)*256 + lane*4;
            ah[mt]  = ldg4(&afb[base]);
            alo[mt] = ldg4(&afb[base + 128]);
        }
        #pragma unroll
        for (int ng = 0; ng < 4; ng++) {
            uint4 nb0, nb1;
            if (ng < 3) {
                nb0 = ldg4(wfw + (ch*16 + 2*ng + 2)*128);
                nb1 = ldg4(wfw + (ch*16 + 2*ng + 3)*128);
            } else if (ch < 7) {
                nb0 = ldg4(wfw + ((ch+1)*16)*128);
                nb1 = ldg4(wfw + ((ch+1)*16 + 1)*128);
            }
            mma_step(acc, ah, alo, b0, b1, 2*ng, 2*ng + 1);
            b0 = nb0; b1 = nb1;
        }
    }

    // ---- fp16 h store ----
    #pragma unroll
    for (int mt = 0; mt < 2; mt++) {
        #pragma unroll
        for (int half = 0; half < 2; half++) {
            int r = m0 + wm*32 + mt*16 + (lane >> 2) + half*8;
            if (r >= M) continue;
            #pragma unroll
            for (int nt = 0; nt < 8; nt++) {
                int c = col0 + wn*64 + nt*8 + 2*(lane & 3);
                __half2 hv = __float22half2_rn(
                    make_float2(acc[mt][nt][half*2 + 0], acc[mt][nt][half*2 + 1]));
                *reinterpret_cast<__half2*>(&g_h[(size_t)r*HF + c]) = hv;
            }
        }
    }
    // ---- fused attention dots ----
    int hh = blockIdx.x;
    float alv[8][2], arv[8][2];
    #pragma unroll
    for (int nt = 0; nt < 8; nt++)
        #pragma unroll
        for (int j = 0; j < 2; j++) {
            int c = wn*64 + nt*8 + 2*(lane & 3) + j;
            alv[nt][j] = __ldg(&al[hh*HIDN + c]);
            arv[nt][j] = __ldg(&ar[hh*HIDN + c]);
        }
    #pragma unroll
    for (int mt = 0; mt < 2; mt++) {
        #pragma unroll
        for (int half = 0; half < 2; half++) {
            float pl = 0.f, pr = 0.f;
            #pragma unroll
            for (int nt = 0; nt < 8; nt++)
                #pragma unroll
                for (int j = 0; j < 2; j++) {
                    float v = acc[mt][nt][half*2 + j];
                    pl += v * alv[nt][j];
                    pr += v * arv[nt][j];
                }
            pl += __shfl_xor_sync(0xffffffffu, pl, 1);
            pl += __shfl_xor_sync(0xffffffffu, pl, 2);
            pr += __shfl_xor_sync(0xffffffffu, pr, 1);
            pr += __shfl_xor_sync(0xffffffffu, pr, 2);
            if ((lane & 3) == 0) {
                int rl = wm*32 + mt*16 + (lane >> 2) + half*8;
                sEl[wn][rl] = pl;
                sEr[wn][rl] = pr;
            }
        }
    }
    __syncthreads();
    if (tid < 128) {
        int r = m0 + tid;
        if (r < M) {
            g_el[r*HH + hh] = sEl[0][tid] + sEl[1][tid];
            g_er[r*HH + hh] = sEr[0][tid] + sEr[1][tid];
        }
    }
}

// ------------- fused MLP: lin1..lin4 in one kernel, frags via smem -------
__global__ __launch_bounds__(256, 2)
void mlp_kernel(const uint32_t* __restrict__ af, const uint32_t* __restrict__ wfbase,
                const float* __restrict__ lb1, const float* __restrict__ lb2,
                const float* __restrict__ lb3, const float* __restrict__ lb4,
                float* __restrict__ xout, int M)
{
    extern __shared__ uint32_t sF[];   // 16384 words = 64 KB
    int tid  = threadIdx.x;
    int lane = tid & 31, warp = tid >> 5;
    int wm = warp >> 1, wn = warp & 1;
    int mblk = blockIdx.x;
    int m0 = mblk*128;

    const float* midbias[3] = {lb1, lb2, lb3};
    const int woff[4] = {WF_L1, WF_L2, WF_L3, WF_L4};

    float acc[2][8][4];
    #pragma unroll
    for (int i = 0; i < 2; i++)
        #pragma unroll
        for (int j = 0; j < 8; j++)
            #pragma unroll
            for (int q = 0; q < 4; q++) acc[i][j][q] = 0.f;

    // ---- layer 1: A from global frags ----
    {
        const uint32_t* afb = af + mblk*16384;
        const uint32_t* wfw = wfbase + woff[0] + wn*8*128 + lane*4;
        uint4 b0 = ldg4(wfw);
        uint4 b1 = ldg4(wfw + 128);
        #pragma unroll 1
        for (int ch = 0; ch < 8; ch++) {
            uint4 ah[2], alo[2];
            #pragma unroll
            for (int mt = 0; mt < 2; mt++) {
                int base = (ch*8 + wm*2 + mt)*256 + lane*4;
                ah[mt]  = ldg4(&afb[base]);
                alo[mt] = ldg4(&afb[base + 128]);
            }
            #pragma unroll
            for (int ng = 0; ng < 4; ng++) {
                uint4 nb0, nb1;
                if (ng < 3) {
                    nb0 = ldg4(wfw + (ch*16 + 2*ng + 2)*128);
                    nb1 = ldg4(wfw + (ch*16 + 2*ng + 3)*128);
                } else if (ch < 7) {
                    nb0 = ldg4(wfw + ((ch+1)*16)*128);
                    nb1 = ldg4(wfw + ((ch+1)*16 + 1)*128);
                }
                mma_step(acc, ah, alo, b0, b1, 2*ng, 2*ng + 1);
                b0 = nb0; b1 = nb1;
            }
        }
    }

    // ---- layers 2..4: frag exchange via smem ----
    #pragma unroll 1
    for (int l = 1; l < 4; l++) {
        const float* bias = midbias[l-1];
        // convert acc (+bias, leaky) -> smem frags; zero acc
        #pragma unroll
        for (int mt = 0; mt < 2; mt++) {
            #pragma unroll
            for (int ng = 0; ng < 4; ng++) {
                int ntE = 2*ng, ntO = 2*ng + 1;
                int cE = wn*64 + ntE*8 + 2*(lane & 3);
                float bE0 = bias[cE],     bE1 = bias[cE + 1];
                float bO0 = bias[cE + 8], bO1 = bias[cE + 9];
                float e0 = acc[mt][ntE][0] + bE0, e1 = acc[mt][ntE][1] + bE1;
                float e2 = acc[mt][ntE][2] + bE0, e3 = acc[mt][ntE][3] + bE1;
                float o0 = acc[mt][ntO][0] + bO0, o1 = acc[mt][ntO][1] + bO1;
                float o2 = acc[mt][ntO][2] + bO0, o3 = acc[mt][ntO][3] + bO1;
                e0 = e0 > 0.f ? e0 : 0.01f*e0;  e1 = e1 > 0.f ? e1 : 0.01f*e1;
                e2 = e2 > 0.f ? e2 : 0.01f*e2;  e3 = e3 > 0.f ? e3 : 0.01f*e3;
                o0 = o0 > 0.f ? o0 : 0.01f*o0;  o1 = o1 > 0.f ? o1 : 0.01f*o1;
                o2 = o2 > 0.f ? o2 : 0.01f*o2;  o3 = o3 > 0.f ? o3 : 0.01f*o3;
                uint32_t l0, l1, l2, l3;
                uint32_t h0 = bfpack2(e0, e1, l0);
                uint32_t h1 = bfpack2(e2, e3, l1);
                uint32_t h2 = bfpack2(o0, o1, l2);
                uint32_t h3 = bfpack2(o2, o3, l3);
                int base = ((wn*4 + ng)*8 + wm*2 + mt)*256 + lane*4;
                *reinterpret_cast<uint4*>(&sF[base])       = make_uint4(h0, h1, h2, h3);
                *reinterpret_cast<uint4*>(&sF[base + 128]) = make_uint4(l0, l1, l2, l3);
                #pragma unroll
                for (int q = 0; q < 4; q++) { acc[mt][ntE][q] = 0.f; acc[mt][ntO][q] = 0.f; }
            }
        }
        __syncthreads();
        const uint32_t* wfw = wfbase + woff[l] + wn*8*128 + lane*4;
        uint4 b0 = ldg4(wfw);
        uint4 b1 = ldg4(wfw + 128);
        #pragma unroll 1
        for (int ch = 0; ch < 8; ch++) {
            uint4 ah[2], alo[2];
            #pragma unroll
            for (int mt = 0; mt < 2; mt++) {
                int base = (ch*8 + wm*2 + mt)*256 + lane*4;
                ah[mt]  = *reinterpret_cast<const uint4*>(&sF[base]);
                alo[mt] = *reinterpret_cast<const uint4*>(&sF[base + 128]);
            }
            #pragma unroll
            for (int ng = 0; ng < 4; ng++) {
                uint4 nb0, nb1;
                if (ng < 3) {
                    nb0 = ldg4(wfw + (ch*16 + 2*ng + 2)*128);
                    nb1 = ldg4(wfw + (ch*16 + 2*ng + 3)*128);
                } else if (ch < 7) {
                    nb0 = ldg4(wfw + ((ch+1)*16)*128);
                    nb1 = ldg4(wfw + ((ch+1)*16 + 1)*128);
                }
                mma_step(acc, ah, alo, b0, b1, 2*ng, 2*ng + 1);
                b0 = nb0; b1 = nb1;
            }
        }
        __syncthreads();   // reads done before next conversion overwrites
    }

    // ---- final: bias lb4 + leaky -> g_x fp32 ----
    #pragma unroll
    for (int mt = 0; mt < 2; mt++) {
        #pragma unroll
        for (int half = 0; half < 2; half++) {
            int r = m0 + wm*32 + mt*16 + (lane >> 2) + half*8;
            if (r >= M) continue;
            #pragma unroll
            for (int nt = 0; nt < 8; nt++) {
                int c = wn*64 + nt*8 + 2*(lane & 3);
                float v0 = acc[mt][nt][half*2 + 0] + lb4[c];
                float v1 = acc[mt][nt][half*2 + 1] + lb4[c + 1];
                v0 = v0 > 0.f ? v0 : 0.01f*v0;
                v1 = v1 > 0.f ? v1 : 0.01f*v1;
                *(float2*)&xout[(size_t)r*HIDN + c] = make_float2(v0, v1);
            }
        }
    }
}

// ---- fused softmax + aggregation, block (96 thr) per node ---------------
__global__ __launch_bounds__(96)
void agg_kernel(const float* __restrict__ bias, uint32_t* __restrict__ fragOut)
{
    __shared__ int    sSrc[CAP];
    __shared__ float  sE[3][CAP];
    __shared__ float4 sh4[3][32];
    int n = blockIdx.x;
    int t = threadIdx.x, head = t >> 5, lane = t & 31;
    int beg = g_rowptr[n], end = g_rowptr[n+1];
    int deg = end - beg;
    int cached = deg < CAP ? deg : CAP;
    for (int j = t; j < cached; j += 96) sSrc[j] = g_srcs[beg + j];
    __syncthreads();

    float er_n = g_er[n*HH + head];
    float mx = -1e30f;
    for (int j = lane; j < deg; j += 32) {
        int s = (j < CAP) ? sSrc[j] : g_srcs[beg + j];
        float v = g_el[s*HH + head] + er_n;
        v = v > 0.f ? v : 0.2f*v;
        if (j < CAP) sE[head][j] = v;
        mx = fmaxf(mx, v);
    }
    #pragma unroll
    for (int o = 16; o; o >>= 1) mx = fmaxf(mx, __shfl_xor_sync(0xffffffffu, mx, o));
    float sum = 0.f;
    for (int j = lane; j < deg; j += 32) {
        float v;
        if (j < CAP) v = sE[head][j];
        else {
            int s = g_srcs[beg + j];
            v = g_el[s*HH + head] + er_n;
            v = v > 0.f ? v : 0.2f*v;
        }
        float e = expf(v - mx);
        if (j < CAP) sE[head][j] = e;
        sum += e;
    }
    #pragma unroll
    for (int o = 16; o; o >>= 1) sum += __shfl_xor_sync(0xffffffffu, sum, o);
    float inv = 1.f / (sum + 1e-9f);
    __syncwarp();

    // weighted gather, unroll 4 (MLP_eff ~4)
    const __half* hb = &g_h[head*HIDN + lane*4];
    float4 a = make_float4(0.f, 0.f, 0.f, 0.f);
    int jn = 0;
    for (; jn + 3 < cached; jn += 4) {
        int   s0 = sSrc[jn],   s1 = sSrc[jn+1], s2 = sSrc[jn+2], s3 = sSrc[jn+3];
        float w0 = sE[head][jn],   w1 = sE[head][jn+1];
        float w2 = sE[head][jn+2], w3 = sE[head][jn+3];
        uint2 u0 = *(const uint2*)&hb[(size_t)s0*HF];
        uint2 u1 = *(const uint2*)&hb[(size_t)s1*HF];
        uint2 u2 = *(const uint2*)&hb[(size_t)s2*HF];
        uint2 u3 = *(const uint2*)&hb[(size_t)s3*HF];
        float2 p00 = __half22float2(*reinterpret_cast<__half2*>(&u0.x));
        float2 p01 = __half22float2(*reinterpret_cast<__half2*>(&u0.y));
        float2 p10 = __half22float2(*reinterpret_cast<__half2*>(&u1.x));
        float2 p11 = __half22float2(*reinterpret_cast<__half2*>(&u1.y));
        float2 p20 = __half22float2(*reinterpret_cast<__half2*>(&u2.x));
        float2 p21 = __half22float2(*reinterpret_cast<__half2*>(&u2.y));
        float2 p30 = __half22float2(*reinterpret_cast<__half2*>(&u3.x));
        float2 p31 = __half22float2(*reinterpret_cast<__half2*>(&u3.y));
        a.x += w0*p00.x + w1*p10.x + w2*p20.x + w3*p30.x;
        a.y += w0*p00.y + w1*p10.y + w2*p20.y + w3*p30.y;
        a.z += w0*p01.x + w1*p11.x + w2*p21.x + w3*p31.x;
        a.w += w0*p01.y + w1*p11.y + w2*p21.y + w3*p31.y;
    }
    for (; jn < cached; jn++) {
        int s = sSrc[jn];
        float w = sE[head][jn];
        uint2 u = *(const uint2*)&hb[(size_t)s*HF];
        float2 p0 = __half22float2(*reinterpret_cast<__half2*>(&u.x));
        float2 p1 = __half22float2(*reinterpret_cast<__half2*>(&u.y));
        a.x += w*p0.x; a.y += w*p0.y; a.z += w*p1.x; a.w += w*p1.y;
    }
    for (int j = beg + CAP; j < end; j++) {      // rare fallback
        int s = g_srcs[j];
        float v = g_el[s*HH + head] + er_n;
        v = v > 0.f ? v : 0.2f*v;
        float w = expf(v - mx);
        uint2 u = *(const uint2*)&hb[(size_t)s*HF];
        float2 p0 = __half22float2(*reinterpret_cast<__half2*>(&u.x));
        float2 p1 = __half22float2(*reinterpret_cast<__half2*>(&u.y));
        a.x += w*p0.x; a.y += w*p0.y; a.z += w*p1.x; a.w += w*p1.y;
    }

    const float4 b4 = *(const float4*)&bias[head*HIDN + lane*4];
    a.x = a.x*inv + b4.x;  a.y = a.y*inv + b4.y;
    a.z = a.z*inv + b4.z;  a.w = a.w*inv + b4.w;
    a.x = a.x > 0.f ? a.x : 0.01f*a.x;
    a.y = a.y > 0.f ? a.y : 0.01f*a.y;
    a.z = a.z > 0.f ? a.z : 0.01f*a.z;
    a.w = a.w > 0.f ? a.w : 0.01f*a.w;
    sh4[head][lane] = a;
    __syncthreads();
    if (t < 32) {
        float4 r0 = sh4[0][t], r1 = sh4[1][t], r2 = sh4[2][t];
        float o[4];
        o[0] = (r0.x + r1.x + r2.x) * (1.f/3.f);
        o[1] = (r0.y + r1.y + r2.y) * (1.f/3.f);
        o[2] = (r0.z + r1.z + r2.z) * (1.f/3.f);
        o[3] = (r0.w + r1.w + r2.w) * (1.f/3.f);
        uint32_t lo01, lo23;
        uint32_t hi01 = bfpack2(o[0], o[1], lo01);
        uint32_t hi23 = bfpack2(o[2], o[3], lo23);
        int a0 = frag_addr(n, t*4);
        int a2 = frag_addr(n, t*4 + 2);
        fragOut[a0]       = hi01;
        fragOut[a0 + 128] = lo01;
        fragOut[a2]       = hi23;
        fragOut[a2 + 128] = lo23;
    }
}

// ---------------- classifier: (N,128)@(128,6)+b, warp per node -----------
__global__ void classifier_kernel(const float* __restrict__ lw5, const float* __restrict__ lb5,
                                  float* __restrict__ out)
{
    int gw   = (blockIdx.x*blockDim.x + threadIdx.x) >> 5;
    int lane = threadIdx.x & 31;
    if (gw >= NN) return;
    const float* xr = &g_x[(size_t)gw*HIDN];
    float acc[NCLS] = {};
    #pragma unroll
    for (int k = lane; k < HIDN; k += 32) {
        float xv = xr[k];
        #pragma unroll
        for (int c = 0; c < NCLS; c++) acc[c] += xv * __ldg(&lw5[k*NCLS + c]);
    }
    #pragma unroll
    for (int c = 0; c < NCLS; c++)
        #pragma unroll
        for (int o = 16; o; o >>= 1) acc[c] += __shfl_xor_sync(0xffffffffu, acc[c], o);
    if (lane == 0) {
        #pragma unroll
        for (int c = 0; c < NCLS; c++) out[gw*NCLS + c] = acc[c] + lb5[c];
    }
}

// -------------------------------------------------------------------------
extern "C" void kernel_launch(void* const* d_in, const int* in_sizes, int n_in,
                              void* d_out, int out_size)
{
    const float* in_feat = (const float*)d_in[0];
    const int*   src     = (const int*)  d_in[1];
    const int*   dst     = (const int*)  d_in[2];
    const float* W1  = (const float*)d_in[3];
    const float* al1 = (const float*)d_in[4];
    const float* ar1 = (const float*)d_in[5];
    const float* b1  = (const float*)d_in[6];
    const float* W2  = (const float*)d_in[7];
    const float* al2 = (const float*)d_in[8];
    const float* ar2 = (const float*)d_in[9];
    const float* b2  = (const float*)d_in[10];
    const float* lw1 = (const float*)d_in[11];
    const float* lb1 = (const float*)d_in[12];
    const float* lw2 = (const float*)d_in[13];
    const float* lb2 = (const float*)d_in[14];
    const float* lw3 = (const float*)d_in[15];
    const float* lb3 = (const float*)d_in[16];
    const float* lw4 = (const float*)d_in[17];
    const float* lb4 = (const float*)d_in[18];
    const float* lw5 = (const float*)d_in[19];
    const float* lb5 = (const float*)d_in[20];
    float* out = (float*)d_out;

    uint32_t *pwf, *pfA;
    float *px;
    cudaGetSymbolAddress((void**)&pwf, g_wf);
    cudaGetSymbolAddress((void**)&pfA, g_afragA);
    cudaGetSymbolAddress((void**)&px,  g_x);

    cudaFuncSetAttribute(mlp_kernel, cudaFuncAttributeMaxDynamicSharedMemorySize, 65536);

    const int TB = 256;
    dim3 g_gat(HF/128, MBLKS);     // (3, 391)

    // pre-splits first (gatgemm stays the 4th launch for ncu)
    presplit_w_kernel<<<(81920 + TB - 1)/TB, TB>>>(W1, W2, lw1, lw2, lw3, lw4);
    presplit_a_kernel<<<(MBLKS*128*64 + TB - 1)/TB, TB>>>(in_feat);
    zero_deg_kernel<<<(NN + TB - 1)/TB, TB>>>();

    // ---- GAT layer 1 GEMM (independent of CSR build) ----
    gatgemm_kernel<<<g_gat, 256>>>(pfA, pwf + WF_W1, NN, al1, ar1);

    // CSR build
    hist_kernel<<<(EE + TB - 1)/TB, TB>>>(dst);
    scan_kernel<<<1, 1024>>>();
    scatter_kernel<<<(EE + TB - 1)/TB, TB>>>(src, dst);

    // ---- GAT layer 1 edge phase ----
    agg_kernel<<<NN, 96>>>(b1, pfA);

    // ---- GAT layer 2 ----
    gatgemm_kernel<<<g_gat, 256>>>(pfA, pwf + WF_W2, NN, al2, ar2);
    agg_kernel<<<NN, 96>>>(b2, pfA);

    // ---- fused MLP (lin1..lin4) ----
    mlp_kernel<<<MBLKS, 256, 65536>>>(pfA, pwf, lb1, lb2, lb3, lb4, px, NN);
    classifier_kernel<<<(NN + 7)/8, 256>>>(lw5, lb5, out);
}